// round 1
// baseline (speedup 1.0000x reference)
#include <cuda_runtime.h>
#include <cstdint>
#include <math.h>

// ---------------- problem constants ----------------
constexpr int kB    = 8;
constexpr int kGrid = 128;            // H = W
constexpr int kNtok = kGrid * kGrid;  // 16384 tokens per batch
constexpr int kC    = 256;
constexpr int kM    = kB * kNtok;     // 131072 total tokens
constexpr int kHid  = 1024;
constexpr int kNWin = kB * 256;       // 2048 windows of 64 tokens

// ---------------- scratch (static device memory; allocation-free) ----------
__device__ float g_big[(size_t)kM * kHid]; // qkv [M,768] then mlp hidden [M,1024]
__device__ float g_a  [(size_t)kM * kC];   // ln1 out (windowed order) / ln2 out
__device__ float g_b  [(size_t)kM * kC];   // attention out (windowed order)
__device__ float g_c  [(size_t)kM * kC];   // x2 = shortcut + attn (natural order)

// windowed token index m -> natural flat token index (b*16384 + h*128 + w)
__device__ __forceinline__ int win_to_nat(int m) {
    int win = m >> 6;
    int t   = m & 63;
    int b   = win >> 8;
    int wi  = win & 255;
    int row = ((wi >> 4) << 3) + (t >> 3);
    int col = ((wi & 15) << 3) + (t & 7);
    return b * kNtok + row * kGrid + col;
}

// ---------------- packed f32x2 FMA helpers ----------------
__device__ __forceinline__ unsigned long long pk2(float lo, float hi) {
    unsigned long long r;
    asm("mov.b64 %0, {%1, %2};" : "=l"(r) : "f"(lo), "f"(hi));
    return r;
}
__device__ __forceinline__ void upk2(unsigned long long v, float& lo, float& hi) {
    asm("mov.b64 {%0, %1}, %2;" : "=f"(lo), "=f"(hi) : "l"(v));
}
__device__ __forceinline__ void fma2(unsigned long long& d,
                                     unsigned long long a,
                                     unsigned long long b) {
    asm("fma.rn.f32x2 %0, %1, %2, %0;" : "+l"(d) : "l"(a), "l"(b));
}

__device__ __forceinline__ float gelu_exact(float x) {
    return 0.5f * x * (1.0f + erff(x * 0.70710678118654752f));
}

// ---------------- LayerNorm: one warp per 256-wide row ----------------
template <bool REMAP_IN>
__global__ __launch_bounds__(256) void ln_kernel(
    const float* __restrict__ in, const float* __restrict__ g,
    const float* __restrict__ b, float* __restrict__ out)
{
    int row  = blockIdx.x * 8 + (threadIdx.x >> 5);
    int lane = threadIdx.x & 31;
    int src  = REMAP_IN ? win_to_nat(row) : row;

    const float4* p = (const float4*)(in + (size_t)src * kC);
    float4 v0 = p[lane];
    float4 v1 = p[lane + 32];

    float s  = v0.x + v0.y + v0.z + v0.w + v1.x + v1.y + v1.z + v1.w;
    float s2 = v0.x*v0.x + v0.y*v0.y + v0.z*v0.z + v0.w*v0.w
             + v1.x*v1.x + v1.y*v1.y + v1.z*v1.z + v1.w*v1.w;
    #pragma unroll
    for (int off = 16; off > 0; off >>= 1) {
        s  += __shfl_xor_sync(0xffffffffu, s,  off);
        s2 += __shfl_xor_sync(0xffffffffu, s2, off);
    }
    float mean = s * (1.0f / kC);
    float var  = s2 * (1.0f / kC) - mean * mean;
    float inv  = rsqrtf(var + 1e-5f);

    const float4* gp = (const float4*)g;
    const float4* bp = (const float4*)b;
    float4 g0 = gp[lane], g1 = gp[lane + 32];
    float4 b0 = bp[lane], b1 = bp[lane + 32];

    float4 o0, o1;
    o0.x = (v0.x - mean) * inv * g0.x + b0.x;
    o0.y = (v0.y - mean) * inv * g0.y + b0.y;
    o0.z = (v0.z - mean) * inv * g0.z + b0.z;
    o0.w = (v0.w - mean) * inv * g0.w + b0.w;
    o1.x = (v1.x - mean) * inv * g1.x + b1.x;
    o1.y = (v1.y - mean) * inv * g1.y + b1.y;
    o1.z = (v1.z - mean) * inv * g1.z + b1.z;
    o1.w = (v1.w - mean) * inv * g1.w + b1.w;

    float4* q = (float4*)(out + (size_t)row * kC);
    q[lane]      = o0;
    q[lane + 32] = o1;
}

// ---------------- GEMM: out[M,N] = A[M,K] @ W[N,K]^T (+ epilogue) ----------
// EPI: 0 = +bias               (qkv)
//      1 = gelu(+bias)         (mlp1)
//      2 = +bias +res, row remapped windowed->natural, N==256 (out-proj)
//      3 = +bias +res, same rows, N==256 (mlp2 -> final output)
template <int EPI>
__global__ __launch_bounds__(256) void gemm_kernel(
    const float* __restrict__ A, const float* __restrict__ W,
    const float* __restrict__ bias, const float* __restrict__ res,
    float* __restrict__ out, int M, int N, int K)
{
    __shared__ float As[16][128];
    __shared__ float Bs[16][128];

    const int bm = blockIdx.y * 128;
    const int bn = blockIdx.x * 128;
    const int tid = threadIdx.x;
    const int tx = tid & 15;   // n-group
    const int ty = tid >> 4;   // m-group

    unsigned long long acc[8][4];
    #pragma unroll
    for (int i = 0; i < 8; i++)
        #pragma unroll
        for (int j = 0; j < 4; j++) acc[i][j] = 0ull;

    const float* Ag = A + (size_t)bm * K;
    const float* Wg = W + (size_t)bn * K;

    for (int k0 = 0; k0 < K; k0 += 16) {
        #pragma unroll
        for (int u = 0; u < 2; u++) {
            int f   = tid + u * 256;       // float4 index in the 128x16 tile
            int row = f >> 2;
            int kq  = f & 3;
            float4 av = *(const float4*)&Ag[(size_t)row * K + k0 + kq * 4];
            float4 bv = *(const float4*)&Wg[(size_t)row * K + k0 + kq * 4];
            As[kq*4+0][row] = av.x; As[kq*4+1][row] = av.y;
            As[kq*4+2][row] = av.z; As[kq*4+3][row] = av.w;
            Bs[kq*4+0][row] = bv.x; Bs[kq*4+1][row] = bv.y;
            Bs[kq*4+2][row] = bv.z; Bs[kq*4+3][row] = bv.w;
        }
        __syncthreads();

        #pragma unroll
        for (int k = 0; k < 16; k++) {
            float4 a0 = *(const float4*)&As[k][ty * 8];
            float4 a1 = *(const float4*)&As[k][ty * 8 + 4];
            float4 c0 = *(const float4*)&Bs[k][tx * 8];
            float4 c1 = *(const float4*)&Bs[k][tx * 8 + 4];
            unsigned long long bb[4] = { pk2(c0.x, c0.y), pk2(c0.z, c0.w),
                                         pk2(c1.x, c1.y), pk2(c1.z, c1.w) };
            float aa[8] = { a0.x, a0.y, a0.z, a0.w, a1.x, a1.y, a1.z, a1.w };
            #pragma unroll
            for (int i = 0; i < 8; i++) {
                unsigned long long a2 = pk2(aa[i], aa[i]);
                #pragma unroll
                for (int j = 0; j < 4; j++) fma2(acc[i][j], a2, bb[j]);
            }
        }
        __syncthreads();
    }

    #pragma unroll
    for (int i = 0; i < 8; i++) {
        int m = bm + ty * 8 + i;
        int orow = (EPI == 2) ? win_to_nat(m) : m;
        #pragma unroll
        for (int j = 0; j < 4; j++) {
            int n0 = bn + tx * 8 + j * 2;
            float lo, hi;
            upk2(acc[i][j], lo, hi);
            lo += bias[n0];
            hi += bias[n0 + 1];
            if (EPI == 1) { lo = gelu_exact(lo); hi = gelu_exact(hi); }
            if (EPI == 2 || EPI == 3) {
                lo += res[(size_t)orow * 256 + n0];
                hi += res[(size_t)orow * 256 + n0 + 1];
            }
            float2 v = make_float2(lo, hi);
            *(float2*)&out[(size_t)orow * N + n0] = v;
        }
    }
}

// ---------------- windowed attention: one block per (window, head) --------
// qkv rows are windowed [m, 768]: q at +0, k at +256, v at +512, head h dims h*32..
__global__ __launch_bounds__(128) void attn_kernel(
    const float* __restrict__ qkv, float* __restrict__ o)
{
    __shared__ float qT[32][68];   // [d][t]
    __shared__ float kT[32][68];   // [d][s]
    __shared__ float vs[64][36];   // [s][d]
    __shared__ float attS[64][68]; // [t][s]

    const int tid  = threadIdx.x;
    const int win  = blockIdx.x >> 3;
    const int head = blockIdx.x & 7;
    const size_t base = (size_t)win * 64 * 768 + head * 32;

    for (int i = tid; i < 64 * 32; i += 128) {
        int t = i >> 5, d = i & 31;
        const float* p = qkv + base + (size_t)t * 768 + d;
        qT[d][t] = p[0];
        kT[d][t] = p[256];
        vs[t][d] = p[512];
    }
    __syncthreads();

    const int rg = tid >> 3;      // 0..15 (rows r0..r0+3)
    const int cg = tid & 7;       // 0..7
    const int r0 = rg * 4;
    const int s0 = cg * 8;

    float sc[4][8];
    #pragma unroll
    for (int i = 0; i < 4; i++)
        #pragma unroll
        for (int j = 0; j < 8; j++) sc[i][j] = 0.0f;

    #pragma unroll
    for (int d = 0; d < 32; d++) {
        float4 qv = *(const float4*)&qT[d][r0];
        float4 k0 = *(const float4*)&kT[d][s0];
        float4 k1 = *(const float4*)&kT[d][s0 + 4];
        float qa[4] = { qv.x, qv.y, qv.z, qv.w };
        float kb[8] = { k0.x, k0.y, k0.z, k0.w, k1.x, k1.y, k1.z, k1.w };
        #pragma unroll
        for (int i = 0; i < 4; i++)
            #pragma unroll
            for (int j = 0; j < 8; j++) sc[i][j] += qa[i] * kb[j];
    }

    const float scale = 0.17677669529663687f;  // 1/sqrt(32)
    #pragma unroll
    for (int i = 0; i < 4; i++) {
        #pragma unroll
        for (int j = 0; j < 8; j++) sc[i][j] *= scale;

        float mx = sc[i][0];
        #pragma unroll
        for (int j = 1; j < 8; j++) mx = fmaxf(mx, sc[i][j]);
        #pragma unroll
        for (int off = 1; off < 8; off <<= 1)
            mx = fmaxf(mx, __shfl_xor_sync(0xffffffffu, mx, off));

        float sum = 0.0f;
        #pragma unroll
        for (int j = 0; j < 8; j++) { sc[i][j] = __expf(sc[i][j] - mx); sum += sc[i][j]; }
        #pragma unroll
        for (int off = 1; off < 8; off <<= 1)
            sum += __shfl_xor_sync(0xffffffffu, sum, off);

        float inv = 1.0f / sum;
        #pragma unroll
        for (int j = 0; j < 8; j++) attS[r0 + i][s0 + j] = sc[i][j] * inv;
    }
    __syncthreads();

    // AV: same rg rows, dg = tid&7 selects d0..d0+3
    const int d0 = (tid & 7) * 4;
    float oacc[4][4];
    #pragma unroll
    for (int i = 0; i < 4; i++)
        #pragma unroll
        for (int j = 0; j < 4; j++) oacc[i][j] = 0.0f;

    #pragma unroll 8
    for (int s = 0; s < 64; s++) {
        float4 vv = *(const float4*)&vs[s][d0];
        float av[4];
        #pragma unroll
        for (int i = 0; i < 4; i++) av[i] = attS[r0 + i][s];
        #pragma unroll
        for (int i = 0; i < 4; i++) {
            oacc[i][0] += av[i] * vv.x;
            oacc[i][1] += av[i] * vv.y;
            oacc[i][2] += av[i] * vv.z;
            oacc[i][3] += av[i] * vv.w;
        }
    }

    #pragma unroll
    for (int i = 0; i < 4; i++) {
        float4 v = make_float4(oacc[i][0], oacc[i][1], oacc[i][2], oacc[i][3]);
        *(float4*)&o[((size_t)(win * 64 + r0 + i)) * kC + head * 32 + d0] = v;
    }
}

// ---------------- launch ----------------
extern "C" void kernel_launch(void* const* d_in, const int* in_sizes, int n_in,
                              void* d_out, int out_size)
{
    const float* x     = (const float*)d_in[0];
    const float* ln1_g = (const float*)d_in[1];
    const float* ln1_b = (const float*)d_in[2];
    const float* in_w  = (const float*)d_in[3];
    const float* in_b  = (const float*)d_in[4];
    const float* out_w = (const float*)d_in[5];
    const float* out_b = (const float*)d_in[6];
    const float* ln2_g = (const float*)d_in[7];
    const float* ln2_b = (const float*)d_in[8];
    const float* w1    = (const float*)d_in[9];
    const float* b1    = (const float*)d_in[10];
    const float* w2    = (const float*)d_in[11];
    const float* b2    = (const float*)d_in[12];
    float* out = (float*)d_out;

    float *big, *a, *bb, *cc;
    cudaGetSymbolAddress((void**)&big, g_big);
    cudaGetSymbolAddress((void**)&a,   g_a);
    cudaGetSymbolAddress((void**)&bb,  g_b);
    cudaGetSymbolAddress((void**)&cc,  g_c);

    // 1) LN1, natural -> windowed order
    ln_kernel<true><<<kM / 8, 256>>>(x, ln1_g, ln1_b, a);
    // 2) QKV projection: [M,256] @ [768,256]^T -> [M,768]
    gemm_kernel<0><<<dim3(768 / 128, kM / 128), 256>>>(a, in_w, in_b, nullptr, big, kM, 768, kC);
    // 3) windowed attention -> [M,256] (windowed order)
    attn_kernel<<<kNWin * 8, 128>>>(big, bb);
    // 4) out-proj + window-reverse + residual -> x2 (natural order)
    gemm_kernel<2><<<dim3(256 / 128, kM / 128), 256>>>(bb, out_w, out_b, x, cc, kM, kC, kC);
    // 5) LN2
    ln_kernel<false><<<kM / 8, 256>>>(cc, ln2_g, ln2_b, a);
    // 6) MLP up + exact GELU: [M,256] @ [1024,256]^T
    gemm_kernel<1><<<dim3(kHid / 128, kM / 128), 256>>>(a, w1, b1, nullptr, big, kM, kHid, kC);
    // 7) MLP down + residual -> final output
    gemm_kernel<3><<<dim3(256 / 128, kM / 128), 256>>>(big, w2, b2, cc, out, kM, kC, kHid);
}

// round 2
// speedup vs baseline: 1.8230x; 1.8230x over previous
#include <cuda_runtime.h>
#include <cstdint>
#include <math.h>

// ---------------- problem constants ----------------
constexpr int kB    = 8;
constexpr int kGrid = 128;            // H = W
constexpr int kNtok = kGrid * kGrid;  // 16384 tokens per batch
constexpr int kC    = 256;
constexpr int kM    = kB * kNtok;     // 131072 total tokens
constexpr int kHid  = 1024;
constexpr int kNWin = kB * 256;       // 2048 windows of 64 tokens

// ---------------- scratch (static device memory; allocation-free) ----------
__device__ float g_big[(size_t)kM * kHid]; // qkv [M,768] then mlp hidden [M,1024]
__device__ float g_a  [(size_t)kM * kC];   // ln1 out (windowed order) / ln2 out
__device__ float g_b  [(size_t)kM * kC];   // attention out (windowed order)
__device__ float g_c  [(size_t)kM * kC];   // x2 = shortcut + attn (natural order)
__device__ float g_w  [786432];            // tf32-rounded weights (all four)

// windowed token index m -> natural flat token index (b*16384 + h*128 + w)
__device__ __forceinline__ int win_to_nat(int m) {
    int win = m >> 6;
    int t   = m & 63;
    int b   = win >> 8;
    int wi  = win & 255;
    int row = ((wi >> 4) << 3) + (t >> 3);
    int col = ((wi & 15) << 3) + (t & 7);
    return b * kNtok + row * kGrid + col;
}

__device__ __forceinline__ uint32_t tf32r(float x) {
    uint32_t r;
    asm("cvt.rna.tf32.f32 %0, %1;" : "=r"(r) : "f"(x));
    return r;
}
__device__ __forceinline__ float tf32f(float x) {
    return __uint_as_float(tf32r(x));
}

__device__ __forceinline__ float gelu_exact(float x) {
    return 0.5f * x * (1.0f + erff(x * 0.70710678118654752f));
}

__device__ __forceinline__ void cpa16(float* s, const float* g) {
    uint32_t sa = (uint32_t)__cvta_generic_to_shared(s);
    asm volatile("cp.async.cg.shared.global [%0], [%1], 16;" :: "r"(sa), "l"(g));
}
__device__ __forceinline__ void cpa_commit() {
    asm volatile("cp.async.commit_group;");
}

// ---------------- tf32 weight rounding ----------------
__global__ __launch_bounds__(256) void cvtw_kernel(const float* __restrict__ w,
                                                   float* __restrict__ o, int n) {
    int i = blockIdx.x * 256 + threadIdx.x;
    if (i < n) o[i] = tf32f(w[i]);
}

// ---------------- LayerNorm: one warp per 256-wide row (tf32-rounds output) --
template <bool REMAP_IN>
__global__ __launch_bounds__(256) void ln_kernel(
    const float* __restrict__ in, const float* __restrict__ g,
    const float* __restrict__ b, float* __restrict__ out)
{
    int row  = blockIdx.x * 8 + (threadIdx.x >> 5);
    int lane = threadIdx.x & 31;
    int src  = REMAP_IN ? win_to_nat(row) : row;

    const float4* p = (const float4*)(in + (size_t)src * kC);
    float4 v0 = p[lane];
    float4 v1 = p[lane + 32];

    float s  = v0.x + v0.y + v0.z + v0.w + v1.x + v1.y + v1.z + v1.w;
    float s2 = v0.x*v0.x + v0.y*v0.y + v0.z*v0.z + v0.w*v0.w
             + v1.x*v1.x + v1.y*v1.y + v1.z*v1.z + v1.w*v1.w;
    #pragma unroll
    for (int off = 16; off > 0; off >>= 1) {
        s  += __shfl_xor_sync(0xffffffffu, s,  off);
        s2 += __shfl_xor_sync(0xffffffffu, s2, off);
    }
    float mean = s * (1.0f / kC);
    float var  = s2 * (1.0f / kC) - mean * mean;
    float inv  = rsqrtf(var + 1e-5f);

    const float4* gp = (const float4*)g;
    const float4* bp = (const float4*)b;
    float4 g0 = gp[lane], g1 = gp[lane + 32];
    float4 b0 = bp[lane], b1 = bp[lane + 32];

    float4 o0, o1;
    o0.x = tf32f((v0.x - mean) * inv * g0.x + b0.x);
    o0.y = tf32f((v0.y - mean) * inv * g0.y + b0.y);
    o0.z = tf32f((v0.z - mean) * inv * g0.z + b0.z);
    o0.w = tf32f((v0.w - mean) * inv * g0.w + b0.w);
    o1.x = tf32f((v1.x - mean) * inv * g1.x + b1.x);
    o1.y = tf32f((v1.y - mean) * inv * g1.y + b1.y);
    o1.z = tf32f((v1.z - mean) * inv * g1.z + b1.z);
    o1.w = tf32f((v1.w - mean) * inv * g1.w + b1.w);

    float4* q = (float4*)(out + (size_t)row * kC);
    q[lane]      = o0;
    q[lane + 32] = o1;
}

// ---------------- tf32 tensor-core GEMM ------------------------------------
// out[M,N] = A[M,K] @ W[N,K]^T (+ epilogue)
// EPI: 0 = +bias (qkv, fp32 out)
//      1 = gelu(+bias), tf32-rounded out (mlp1)
//      2 = +bias +res, row remapped windowed->natural, N==256 (out-proj)
//      3 = +bias +res (mlp2 -> final output)
// A and W must already be tf32-rounded values (low mantissa bits zero).
constexpr int kStrideS = 24;  // floats per SMEM row (conflict-free frag loads)

template <int EPI>
__global__ __launch_bounds__(256) void tgemm_kernel(
    const float* __restrict__ A, const float* __restrict__ W,
    const float* __restrict__ bias, const float* __restrict__ res,
    float* __restrict__ out, int M, int N, int K)
{
    __shared__ float As[2][128 * kStrideS];
    __shared__ float Bs[2][128 * kStrideS];

    const int bm   = blockIdx.y * 128;
    const int bn   = blockIdx.x * 128;
    const int tid  = threadIdx.x;
    const int warp = tid >> 5;
    const int lane = tid & 31;
    const int grp  = lane >> 2;
    const int tig  = lane & 3;
    const int wm   = warp & 1;   // 2 warp rows (64 each)
    const int wn   = warp >> 1;  // 4 warp cols (32 each)

    const float* Ag = A + (size_t)bm * K;
    const float* Wg = W + (size_t)bn * K;

    float c[4][4][4];
    #pragma unroll
    for (int i = 0; i < 4; i++)
        #pragma unroll
        for (int j = 0; j < 4; j++)
            #pragma unroll
            for (int r = 0; r < 4; r++) c[i][j][r] = 0.0f;

    const int T = K >> 4;  // BK=16 stages

    // prologue: stage 0
    {
        #pragma unroll
        for (int u = 0; u < 2; u++) {
            int idx = tid + u * 256;
            int row = idx >> 2;
            int q   = idx & 3;
            cpa16(&As[0][row * kStrideS + q * 4], Ag + (size_t)row * K + q * 4);
            cpa16(&Bs[0][row * kStrideS + q * 4], Wg + (size_t)row * K + q * 4);
        }
        cpa_commit();
    }

    for (int t = 0; t < T; t++) {
        if (t + 1 < T) {
            int k0  = (t + 1) << 4;
            int buf = (t + 1) & 1;
            #pragma unroll
            for (int u = 0; u < 2; u++) {
                int idx = tid + u * 256;
                int row = idx >> 2;
                int q   = idx & 3;
                cpa16(&As[buf][row * kStrideS + q * 4], Ag + (size_t)row * K + k0 + q * 4);
                cpa16(&Bs[buf][row * kStrideS + q * 4], Wg + (size_t)row * K + k0 + q * 4);
            }
            cpa_commit();
            asm volatile("cp.async.wait_group 1;");
        } else {
            asm volatile("cp.async.wait_group 0;");
        }
        __syncthreads();

        const float* as = As[t & 1];
        const float* bs = Bs[t & 1];

        #pragma unroll
        for (int ks = 0; ks < 2; ks++) {
            uint32_t af[4][4];
            uint32_t bf[4][2];
            const int kcol = ks * 8 + 2 * tig;
            #pragma unroll
            for (int i = 0; i < 4; i++) {
                int r = wm * 64 + i * 16 + grp;
                float2 lo = *(const float2*)&as[r * kStrideS + kcol];
                float2 hi = *(const float2*)&as[(r + 8) * kStrideS + kcol];
                af[i][0] = __float_as_uint(lo.x);
                af[i][1] = __float_as_uint(hi.x);
                af[i][2] = __float_as_uint(lo.y);
                af[i][3] = __float_as_uint(hi.y);
            }
            #pragma unroll
            for (int j = 0; j < 4; j++) {
                int n = wn * 32 + j * 8 + grp;
                float2 bv = *(const float2*)&bs[n * kStrideS + kcol];
                bf[j][0] = __float_as_uint(bv.x);
                bf[j][1] = __float_as_uint(bv.y);
            }
            #pragma unroll
            for (int i = 0; i < 4; i++)
                #pragma unroll
                for (int j = 0; j < 4; j++) {
                    asm volatile(
                        "mma.sync.aligned.m16n8k8.row.col.f32.tf32.tf32.f32 "
                        "{%0,%1,%2,%3}, {%4,%5,%6,%7}, {%8,%9}, {%0,%1,%2,%3};"
                        : "+f"(c[i][j][0]), "+f"(c[i][j][1]),
                          "+f"(c[i][j][2]), "+f"(c[i][j][3])
                        : "r"(af[i][0]), "r"(af[i][1]), "r"(af[i][2]), "r"(af[i][3]),
                          "r"(bf[j][0]), "r"(bf[j][1]));
                }
        }
        __syncthreads();
    }

    // ---- epilogue ----
    #pragma unroll
    for (int i = 0; i < 4; i++) {
        int mrow0 = bm + wm * 64 + i * 16 + grp;
        int mrow1 = mrow0 + 8;
        int or0 = (EPI == 2) ? win_to_nat(mrow0) : mrow0;
        int or1 = (EPI == 2) ? win_to_nat(mrow1) : mrow1;
        #pragma unroll
        for (int j = 0; j < 4; j++) {
            int col = bn + wn * 32 + j * 8 + 2 * tig;
            float2 bv = *(const float2*)&bias[col];
            float v0 = c[i][j][0] + bv.x;
            float v1 = c[i][j][1] + bv.y;
            float v2 = c[i][j][2] + bv.x;
            float v3 = c[i][j][3] + bv.y;
            if (EPI == 1) {
                v0 = tf32f(gelu_exact(v0));
                v1 = tf32f(gelu_exact(v1));
                v2 = tf32f(gelu_exact(v2));
                v3 = tf32f(gelu_exact(v3));
            }
            if (EPI == 2 || EPI == 3) {
                float2 r0 = *(const float2*)&res[(size_t)or0 * 256 + col];
                float2 r1 = *(const float2*)&res[(size_t)or1 * 256 + col];
                v0 += r0.x; v1 += r0.y;
                v2 += r1.x; v3 += r1.y;
            }
            *(float2*)&out[(size_t)or0 * N + col] = make_float2(v0, v1);
            *(float2*)&out[(size_t)or1 * N + col] = make_float2(v2, v3);
        }
    }
}

// ---------------- windowed attention: one block per (window, head) --------
// qkv rows are windowed [m, 768]: q at +0, k at +256, v at +512, head h dims h*32..
__global__ __launch_bounds__(128) void attn_kernel(
    const float* __restrict__ qkv, float* __restrict__ o)
{
    __shared__ float qT[32][68];   // [d][t]
    __shared__ float kT[32][68];   // [d][s]
    __shared__ float vs[64][36];   // [s][d]
    __shared__ float attS[64][68]; // [t][s]

    const int tid  = threadIdx.x;
    const int win  = blockIdx.x >> 3;
    const int head = blockIdx.x & 7;
    const size_t base = (size_t)win * 64 * 768 + head * 32;

    for (int i = tid; i < 64 * 32; i += 128) {
        int t = i >> 5, d = i & 31;
        const float* p = qkv + base + (size_t)t * 768 + d;
        qT[d][t] = p[0];
        kT[d][t] = p[256];
        vs[t][d] = p[512];
    }
    __syncthreads();

    const int rg = tid >> 3;      // 0..15 (rows r0..r0+3)
    const int cg = tid & 7;       // 0..7
    const int r0 = rg * 4;
    const int s0 = cg * 8;

    float sc[4][8];
    #pragma unroll
    for (int i = 0; i < 4; i++)
        #pragma unroll
        for (int j = 0; j < 8; j++) sc[i][j] = 0.0f;

    #pragma unroll
    for (int d = 0; d < 32; d++) {
        float4 qv = *(const float4*)&qT[d][r0];
        float4 k0 = *(const float4*)&kT[d][s0];
        float4 k1 = *(const float4*)&kT[d][s0 + 4];
        float qa[4] = { qv.x, qv.y, qv.z, qv.w };
        float kb[8] = { k0.x, k0.y, k0.z, k0.w, k1.x, k1.y, k1.z, k1.w };
        #pragma unroll
        for (int i = 0; i < 4; i++)
            #pragma unroll
            for (int j = 0; j < 8; j++) sc[i][j] += qa[i] * kb[j];
    }

    const float scale = 0.17677669529663687f;  // 1/sqrt(32)
    #pragma unroll
    for (int i = 0; i < 4; i++) {
        #pragma unroll
        for (int j = 0; j < 8; j++) sc[i][j] *= scale;

        float mx = sc[i][0];
        #pragma unroll
        for (int j = 1; j < 8; j++) mx = fmaxf(mx, sc[i][j]);
        #pragma unroll
        for (int off = 1; off < 8; off <<= 1)
            mx = fmaxf(mx, __shfl_xor_sync(0xffffffffu, mx, off));

        float sum = 0.0f;
        #pragma unroll
        for (int j = 0; j < 8; j++) { sc[i][j] = __expf(sc[i][j] - mx); sum += sc[i][j]; }
        #pragma unroll
        for (int off = 1; off < 8; off <<= 1)
            sum += __shfl_xor_sync(0xffffffffu, sum, off);

        float inv = 1.0f / sum;
        #pragma unroll
        for (int j = 0; j < 8; j++) attS[r0 + i][s0 + j] = sc[i][j] * inv;
    }
    __syncthreads();

    // AV: same rg rows, dg = tid&7 selects d0..d0+3
    const int d0 = (tid & 7) * 4;
    float oacc[4][4];
    #pragma unroll
    for (int i = 0; i < 4; i++)
        #pragma unroll
        for (int j = 0; j < 4; j++) oacc[i][j] = 0.0f;

    #pragma unroll 8
    for (int s = 0; s < 64; s++) {
        float4 vv = *(const float4*)&vs[s][d0];
        float av[4];
        #pragma unroll
        for (int i = 0; i < 4; i++) av[i] = attS[r0 + i][s];
        #pragma unroll
        for (int i = 0; i < 4; i++) {
            oacc[i][0] += av[i] * vv.x;
            oacc[i][1] += av[i] * vv.y;
            oacc[i][2] += av[i] * vv.z;
            oacc[i][3] += av[i] * vv.w;
        }
    }

    #pragma unroll
    for (int i = 0; i < 4; i++) {
        float4 v = make_float4(tf32f(oacc[i][0]), tf32f(oacc[i][1]),
                               tf32f(oacc[i][2]), tf32f(oacc[i][3]));
        *(float4*)&o[((size_t)(win * 64 + r0 + i)) * kC + head * 32 + d0] = v;
    }
}

// ---------------- launch ----------------
extern "C" void kernel_launch(void* const* d_in, const int* in_sizes, int n_in,
                              void* d_out, int out_size)
{
    const float* x     = (const float*)d_in[0];
    const float* ln1_g = (const float*)d_in[1];
    const float* ln1_b = (const float*)d_in[2];
    const float* in_w  = (const float*)d_in[3];
    const float* in_b  = (const float*)d_in[4];
    const float* out_w = (const float*)d_in[5];
    const float* out_b = (const float*)d_in[6];
    const float* ln2_g = (const float*)d_in[7];
    const float* ln2_b = (const float*)d_in[8];
    const float* w1    = (const float*)d_in[9];
    const float* b1    = (const float*)d_in[10];
    const float* w2    = (const float*)d_in[11];
    const float* b2    = (const float*)d_in[12];
    float* out = (float*)d_out;

    float *big, *a, *bb, *cc, *w;
    cudaGetSymbolAddress((void**)&big, g_big);
    cudaGetSymbolAddress((void**)&a,   g_a);
    cudaGetSymbolAddress((void**)&bb,  g_b);
    cudaGetSymbolAddress((void**)&cc,  g_c);
    cudaGetSymbolAddress((void**)&w,   g_w);

    float* w_in  = w;            // 768*256 = 196608
    float* w_out = w + 196608;   // 256*256 = 65536
    float* w_1   = w + 262144;   // 1024*256 = 262144
    float* w_2   = w + 524288;   // 256*1024 = 262144

    // 0) tf32-round weights
    cvtw_kernel<<<(196608 + 255) / 256, 256>>>(in_w,  w_in,  196608);
    cvtw_kernel<<<(65536  + 255) / 256, 256>>>(out_w, w_out, 65536);
    cvtw_kernel<<<(262144 + 255) / 256, 256>>>(w1,    w_1,   262144);
    cvtw_kernel<<<(262144 + 255) / 256, 256>>>(w2,    w_2,   262144);

    // 1) LN1, natural -> windowed order (tf32-rounded)
    ln_kernel<true><<<kM / 8, 256>>>(x, ln1_g, ln1_b, a);
    // 2) QKV projection: [M,256] @ [768,256]^T -> [M,768]
    tgemm_kernel<0><<<dim3(768 / 128, kM / 128), 256>>>(a, w_in, in_b, nullptr, big, kM, 768, kC);
    // 3) windowed attention -> [M,256] (windowed order, tf32-rounded)
    attn_kernel<<<kNWin * 8, 128>>>(big, bb);
    // 4) out-proj + window-reverse + residual -> x2 (natural order, fp32)
    tgemm_kernel<2><<<dim3(256 / 128, kM / 128), 256>>>(bb, w_out, out_b, x, cc, kM, kC, kC);
    // 5) LN2 (tf32-rounded)
    ln_kernel<false><<<kM / 8, 256>>>(cc, ln2_g, ln2_b, a);
    // 6) MLP up + exact GELU: [M,256] @ [1024,256]^T (tf32-rounded out)
    tgemm_kernel<1><<<dim3(kHid / 128, kM / 128), 256>>>(a, w_1, b1, nullptr, big, kM, kHid, kC);
    // 7) MLP down + residual -> final output (fp32)
    tgemm_kernel<3><<<dim3(256 / 128, kM / 128), 256>>>(big, w_2, b2, cc, out, kM, kC, kHid);
}

// round 4
// speedup vs baseline: 4.2316x; 2.3213x over previous
#include <cuda_runtime.h>
#include <cuda_fp16.h>
#include <cstdint>
#include <math.h>

// ---------------- problem constants ----------------
constexpr int kB    = 8;
constexpr int kGrid = 128;
constexpr int kNtok = kGrid * kGrid;
constexpr int kC    = 256;
constexpr int kM    = kB * kNtok;     // 131072 tokens
constexpr int kHid  = 1024;
constexpr int kNWin = kB * 256;       // 2048 windows

// ---------------- scratch ----------------
__device__ __half g_big[(size_t)kM * kHid]; // qkv [M,768] halves, then mlp hidden [M,1024]
__device__ __half g_a  [(size_t)kM * kC];   // ln out (half)
__device__ __half g_b  [(size_t)kM * kC];   // attn out (half)
__device__ float  g_c  [(size_t)kM * kC];   // x2 residual (fp32)
__device__ __half g_w  [786432];            // fp16 weights

__device__ __forceinline__ int win_to_nat(int m) {
    int win = m >> 6;
    int t   = m & 63;
    int b   = win >> 8;
    int wi  = win & 255;
    int row = ((wi >> 4) << 3) + (t >> 3);
    int col = ((wi & 15) << 3) + (t & 7);
    return b * kNtok + row * kGrid + col;
}

__device__ __forceinline__ float gelu_exact(float x) {
    return 0.5f * x * (1.0f + erff(x * 0.70710678118654752f));
}

__device__ __forceinline__ void cpa16(__half* s, const __half* g) {
    uint32_t sa = (uint32_t)__cvta_generic_to_shared(s);
    asm volatile("cp.async.cg.shared.global [%0], [%1], 16;" :: "r"(sa), "l"(g));
}

// ---------------- weight conversion ----------------
__global__ __launch_bounds__(256) void cvtw_kernel(const float* __restrict__ w,
                                                   __half* __restrict__ o, int n) {
    int i = blockIdx.x * 256 + threadIdx.x;
    if (i < n) o[i] = __float2half(w[i]);
}

// ---------------- LayerNorm: one warp per row, fp32 in, fp16 out ----------
template <bool REMAP_IN>
__global__ __launch_bounds__(256) void ln_kernel(
    const float* __restrict__ in, const float* __restrict__ g,
    const float* __restrict__ b, __half* __restrict__ out)
{
    int row  = blockIdx.x * 8 + (threadIdx.x >> 5);
    int lane = threadIdx.x & 31;
    int src  = REMAP_IN ? win_to_nat(row) : row;

    const float4* p = (const float4*)(in + (size_t)src * kC);
    float4 v0 = p[lane];
    float4 v1 = p[lane + 32];

    float s  = v0.x + v0.y + v0.z + v0.w + v1.x + v1.y + v1.z + v1.w;
    float s2 = v0.x*v0.x + v0.y*v0.y + v0.z*v0.z + v0.w*v0.w
             + v1.x*v1.x + v1.y*v1.y + v1.z*v1.z + v1.w*v1.w;
    #pragma unroll
    for (int off = 16; off > 0; off >>= 1) {
        s  += __shfl_xor_sync(0xffffffffu, s,  off);
        s2 += __shfl_xor_sync(0xffffffffu, s2, off);
    }
    float mean = s * (1.0f / kC);
    float var  = s2 * (1.0f / kC) - mean * mean;
    float inv  = rsqrtf(var + 1e-5f);

    const float4* gp = (const float4*)g;
    const float4* bp = (const float4*)b;
    float4 g0 = gp[lane], g1 = gp[lane + 32];
    float4 b0 = bp[lane], b1 = bp[lane + 32];

    __half2 h0 = __floats2half2_rn((v0.x - mean) * inv * g0.x + b0.x,
                                   (v0.y - mean) * inv * g0.y + b0.y);
    __half2 h1 = __floats2half2_rn((v0.z - mean) * inv * g0.z + b0.z,
                                   (v0.w - mean) * inv * g0.w + b0.w);
    __half2 h2 = __floats2half2_rn((v1.x - mean) * inv * g1.x + b1.x,
                                   (v1.y - mean) * inv * g1.y + b1.y);
    __half2 h3 = __floats2half2_rn((v1.z - mean) * inv * g1.z + b1.z,
                                   (v1.w - mean) * inv * g1.w + b1.w);

    // lane covers elements [lane*4, lane*4+3] and [128 + lane*4 ...]
    __half2* q = (__half2*)(out + (size_t)row * kC);
    q[lane * 2]          = h0;
    q[lane * 2 + 1]      = h1;
    q[64 + lane * 2]     = h2;
    q[64 + lane * 2 + 1] = h3;
}

// ---------------- fp16 tensor-core GEMM: out = A[M,K] @ W[N,K]^T + epi ----
// EPI: 0=+bias, half out (qkv)   1=gelu(+bias), half out (mlp1)
//      2=+bias+res fp32 out, rows win->nat (out-proj)   3=+bias+res fp32 out
constexpr int kStrH = 48;  // halves per SMEM row (24 words: conflict-free LDS.64)

template <int EPI>
__global__ __launch_bounds__(256) void hgemm_kernel(
    const __half* __restrict__ A, const __half* __restrict__ W,
    const float* __restrict__ bias, const float* __restrict__ res,
    void* __restrict__ out_v, int M, int N, int K)
{
    __shared__ __half As[2][128 * kStrH];
    __shared__ __half Bs[2][128 * kStrH];

    const int bm   = blockIdx.y * 128;
    const int bn   = blockIdx.x * 128;
    const int tid  = threadIdx.x;
    const int warp = tid >> 5;
    const int lane = tid & 31;
    const int grp  = lane >> 2;
    const int tig  = lane & 3;
    const int wm   = warp & 1;   // 2 warp rows of 64
    const int wn   = warp >> 1;  // 4 warp cols of 32

    const __half* Ag = A + (size_t)bm * K;
    const __half* Wg = W + (size_t)bn * K;

    float c[4][4][4];
    #pragma unroll
    for (int i = 0; i < 4; i++)
        #pragma unroll
        for (int j = 0; j < 4; j++)
            #pragma unroll
            for (int r = 0; r < 4; r++) c[i][j][r] = 0.0f;

    const int T = K >> 5;  // BK = 32

    // prologue: stage 0  (128 rows x 32 halves per matrix; 16B = 8 halves)
    #pragma unroll
    for (int u = 0; u < 2; u++) {
        int idx = tid + u * 256;
        int row = idx >> 2;
        int ch  = idx & 3;
        cpa16(&As[0][row * kStrH + ch * 8], Ag + (size_t)row * K + ch * 8);
        cpa16(&Bs[0][row * kStrH + ch * 8], Wg + (size_t)row * K + ch * 8);
    }
    asm volatile("cp.async.commit_group;");

    for (int t = 0; t < T; t++) {
        if (t + 1 < T) {
            int k0  = (t + 1) << 5;
            int buf = (t + 1) & 1;
            #pragma unroll
            for (int u = 0; u < 2; u++) {
                int idx = tid + u * 256;
                int row = idx >> 2;
                int ch  = idx & 3;
                cpa16(&As[buf][row * kStrH + ch * 8], Ag + (size_t)row * K + k0 + ch * 8);
                cpa16(&Bs[buf][row * kStrH + ch * 8], Wg + (size_t)row * K + k0 + ch * 8);
            }
            asm volatile("cp.async.commit_group;");
            asm volatile("cp.async.wait_group 1;");
        } else {
            asm volatile("cp.async.wait_group 0;");
        }
        __syncthreads();

        const __half* as = As[t & 1];
        const __half* bs = Bs[t & 1];

        #pragma unroll
        for (int kb = 0; kb < 2; kb++) {
            uint32_t af[4][4];
            uint32_t bf[4][2];
            const int kcol = kb * 16 + tig * 4;   // halves
            #pragma unroll
            for (int i = 0; i < 4; i++) {
                int r = wm * 64 + i * 16 + grp;
                uint2 lo = *(const uint2*)&as[r * kStrH + kcol];
                uint2 hi = *(const uint2*)&as[(r + 8) * kStrH + kcol];
                af[i][0] = lo.x; af[i][1] = hi.x;
                af[i][2] = lo.y; af[i][3] = hi.y;
            }
            #pragma unroll
            for (int j = 0; j < 4; j++) {
                int n = wn * 32 + j * 8 + grp;
                uint2 bv = *(const uint2*)&bs[n * kStrH + kcol];
                bf[j][0] = bv.x; bf[j][1] = bv.y;
            }
            #pragma unroll
            for (int i = 0; i < 4; i++)
                #pragma unroll
                for (int j = 0; j < 4; j++) {
                    asm volatile(
                        "mma.sync.aligned.m16n8k16.row.col.f32.f16.f16.f32 "
                        "{%0,%1,%2,%3}, {%4,%5,%6,%7}, {%8,%9}, {%0,%1,%2,%3};"
                        : "+f"(c[i][j][0]), "+f"(c[i][j][1]),
                          "+f"(c[i][j][2]), "+f"(c[i][j][3])
                        : "r"(af[i][0]), "r"(af[i][1]), "r"(af[i][2]), "r"(af[i][3]),
                          "r"(bf[j][0]), "r"(bf[j][1]));
                }
        }
        __syncthreads();
    }

    // ---- epilogue ----
    #pragma unroll
    for (int i = 0; i < 4; i++) {
        int mrow0 = bm + wm * 64 + i * 16 + grp;
        int mrow1 = mrow0 + 8;
        int or0 = (EPI == 2) ? win_to_nat(mrow0) : mrow0;
        int or1 = (EPI == 2) ? win_to_nat(mrow1) : mrow1;
        #pragma unroll
        for (int j = 0; j < 4; j++) {
            int col = bn + wn * 32 + j * 8 + 2 * tig;
            float2 bv = *(const float2*)&bias[col];
            float v0 = c[i][j][0] + bv.x;
            float v1 = c[i][j][1] + bv.y;
            float v2 = c[i][j][2] + bv.x;
            float v3 = c[i][j][3] + bv.y;
            if (EPI == 0) {
                __half* out = (__half*)out_v;
                *(__half2*)&out[(size_t)or0 * N + col] = __floats2half2_rn(v0, v1);
                *(__half2*)&out[(size_t)or1 * N + col] = __floats2half2_rn(v2, v3);
            } else if (EPI == 1) {
                __half* out = (__half*)out_v;
                *(__half2*)&out[(size_t)or0 * N + col] =
                    __floats2half2_rn(gelu_exact(v0), gelu_exact(v1));
                *(__half2*)&out[(size_t)or1 * N + col] =
                    __floats2half2_rn(gelu_exact(v2), gelu_exact(v3));
            } else {
                float* out = (float*)out_v;
                float2 r0 = *(const float2*)&res[(size_t)or0 * 256 + col];
                float2 r1 = *(const float2*)&res[(size_t)or1 * 256 + col];
                *(float2*)&out[(size_t)or0 * N + col] = make_float2(v0 + r0.x, v1 + r0.y);
                *(float2*)&out[(size_t)or1 * N + col] = make_float2(v2 + r1.x, v3 + r1.y);
            }
        }
    }
}

// ---------------- windowed attention: one block per (window, head) --------
// qkv half rows [m, 768]: q +0, k +256, v +512; head h dims h*32..h*32+31
__global__ __launch_bounds__(128) void attn_kernel(
    const __half* __restrict__ qkv, __half* __restrict__ o)
{
    __shared__ float qT[32][68];
    __shared__ float kT[32][68];
    __shared__ float vs[64][36];
    __shared__ float attS[64][68];

    const int tid  = threadIdx.x;
    const int win  = blockIdx.x >> 3;
    const int head = blockIdx.x & 7;
    const size_t base = (size_t)win * 64 * 768 + head * 32;

    for (int i = tid; i < 64 * 16; i += 128) {
        int t = i >> 4, d2 = (i & 15) * 2;
        const __half2* p = (const __half2*)(qkv + base + (size_t)t * 768 + d2);
        float2 qv = __half22float2(p[0]);
        float2 kv = __half22float2(p[128]);   // +256 halves
        float2 vv = __half22float2(p[256]);   // +512 halves
        qT[d2][t] = qv.x; qT[d2 + 1][t] = qv.y;
        kT[d2][t] = kv.x; kT[d2 + 1][t] = kv.y;
        vs[t][d2] = vv.x; vs[t][d2 + 1] = vv.y;
    }
    __syncthreads();

    const int rg = tid >> 3;
    const int cg = tid & 7;
    const int r0 = rg * 4;
    const int s0 = cg * 8;

    float sc[4][8];
    #pragma unroll
    for (int i = 0; i < 4; i++)
        #pragma unroll
        for (int j = 0; j < 8; j++) sc[i][j] = 0.0f;

    #pragma unroll
    for (int d = 0; d < 32; d++) {
        float4 qv = *(const float4*)&qT[d][r0];
        float4 k0 = *(const float4*)&kT[d][s0];
        float4 k1 = *(const float4*)&kT[d][s0 + 4];
        float qa[4] = { qv.x, qv.y, qv.z, qv.w };
        float kb[8] = { k0.x, k0.y, k0.z, k0.w, k1.x, k1.y, k1.z, k1.w };
        #pragma unroll
        for (int i = 0; i < 4; i++)
            #pragma unroll
            for (int j = 0; j < 8; j++) sc[i][j] += qa[i] * kb[j];
    }

    const float scale = 0.17677669529663687f;
    #pragma unroll
    for (int i = 0; i < 4; i++) {
        #pragma unroll
        for (int j = 0; j < 8; j++) sc[i][j] *= scale;
        float mx = sc[i][0];
        #pragma unroll
        for (int j = 1; j < 8; j++) mx = fmaxf(mx, sc[i][j]);
        #pragma unroll
        for (int off = 1; off < 8; off <<= 1)
            mx = fmaxf(mx, __shfl_xor_sync(0xffffffffu, mx, off));
        float sum = 0.0f;
        #pragma unroll
        for (int j = 0; j < 8; j++) { sc[i][j] = __expf(sc[i][j] - mx); sum += sc[i][j]; }
        #pragma unroll
        for (int off = 1; off < 8; off <<= 1)
            sum += __shfl_xor_sync(0xffffffffu, sum, off);
        float inv = 1.0f / sum;
        #pragma unroll
        for (int j = 0; j < 8; j++) attS[r0 + i][s0 + j] = sc[i][j] * inv;
    }
    __syncthreads();

    const int d0 = (tid & 7) * 4;
    float oacc[4][4];
    #pragma unroll
    for (int i = 0; i < 4; i++)
        #pragma unroll
        for (int j = 0; j < 4; j++) oacc[i][j] = 0.0f;

    #pragma unroll 8
    for (int s = 0; s < 64; s++) {
        float4 vv = *(const float4*)&vs[s][d0];
        float av[4];
        #pragma unroll
        for (int i = 0; i < 4; i++) av[i] = attS[r0 + i][s];
        #pragma unroll
        for (int i = 0; i < 4; i++) {
            oacc[i][0] += av[i] * vv.x;
            oacc[i][1] += av[i] * vv.y;
            oacc[i][2] += av[i] * vv.z;
            oacc[i][3] += av[i] * vv.w;
        }
    }

    #pragma unroll
    for (int i = 0; i < 4; i++) {
        __half2 h0 = __floats2half2_rn(oacc[i][0], oacc[i][1]);
        __half2 h1 = __floats2half2_rn(oacc[i][2], oacc[i][3]);
        __half2* q = (__half2*)&o[((size_t)(win * 64 + r0 + i)) * kC + head * 32 + d0];
        q[0] = h0;
        q[1] = h1;
    }
}

// ---------------- launch ----------------
extern "C" void kernel_launch(void* const* d_in, const int* in_sizes, int n_in,
                              void* d_out, int out_size)
{
    const float* x     = (const float*)d_in[0];
    const float* ln1_g = (const float*)d_in[1];
    const float* ln1_b = (const float*)d_in[2];
    const float* in_w  = (const float*)d_in[3];
    const float* in_b  = (const float*)d_in[4];
    const float* out_w = (const float*)d_in[5];
    const float* out_b = (const float*)d_in[6];
    const float* ln2_g = (const float*)d_in[7];
    const float* ln2_b = (const float*)d_in[8];
    const float* w1    = (const float*)d_in[9];
    const float* b1    = (const float*)d_in[10];
    const float* w2    = (const float*)d_in[11];
    const float* b2    = (const float*)d_in[12];
    float* out = (float*)d_out;

    __half *big, *a, *bb, *w;
    float *cc;
    cudaGetSymbolAddress((void**)&big, g_big);
    cudaGetSymbolAddress((void**)&a,   g_a);
    cudaGetSymbolAddress((void**)&bb,  g_b);
    cudaGetSymbolAddress((void**)&cc,  g_c);
    cudaGetSymbolAddress((void**)&w,   g_w);

    __half* w_in  = w;            // 768*256
    __half* w_out = w + 196608;   // 256*256
    __half* w_1   = w + 262144;   // 1024*256
    __half* w_2   = w + 524288;   // 256*1024

    // 0) fp16 weights
    cvtw_kernel<<<768, 256>>>(in_w,  w_in,  196608);
    cvtw_kernel<<<256, 256>>>(out_w, w_out, 65536);
    cvtw_kernel<<<1024, 256>>>(w1,   w_1,   262144);
    cvtw_kernel<<<1024, 256>>>(w2,   w_2,   262144);

    // 1) LN1, natural -> windowed order, half out
    ln_kernel<true><<<kM / 8, 256>>>(x, ln1_g, ln1_b, a);
    // 2) QKV projection: [M,256] @ [768,256]^T -> half [M,768]
    hgemm_kernel<0><<<dim3(6, kM / 128), 256>>>(a, w_in, in_b, nullptr, big, kM, 768, kC);
    // 3) windowed attention -> half [M,256] (windowed order)
    attn_kernel<<<kNWin * 8, 128>>>(big, bb);
    // 4) out-proj + window-reverse + residual -> fp32 x2 (natural order)
    hgemm_kernel<2><<<dim3(2, kM / 128), 256>>>(bb, w_out, out_b, x, cc, kM, kC, kC);
    // 5) LN2, half out
    ln_kernel<false><<<kM / 8, 256>>>(cc, ln2_g, ln2_b, a);
    // 6) MLP up + exact GELU -> half [M,1024]
    hgemm_kernel<1><<<dim3(8, kM / 128), 256>>>(a, w_1, b1, nullptr, big, kM, kHid, kC);
    // 7) MLP down + residual -> fp32 final output
    hgemm_kernel<3><<<dim3(2, kM / 128), 256>>>(big, w_2, b2, cc, out, kM, kC, kHid);
}

// round 5
// speedup vs baseline: 4.6173x; 1.0911x over previous
#include <cuda_runtime.h>
#include <cuda_fp16.h>
#include <cstdint>
#include <math.h>

// ---------------- problem constants ----------------
constexpr int kB    = 8;
constexpr int kGrid = 128;
constexpr int kNtok = kGrid * kGrid;
constexpr int kC    = 256;
constexpr int kM    = kB * kNtok;     // 131072 tokens
constexpr int kHid  = 1024;
constexpr int kNWin = kB * 256;       // 2048 windows

// ---------------- scratch ----------------
__device__ __half g_big[(size_t)kM * kHid];
__device__ __half g_a  [(size_t)kM * kC];
__device__ __half g_b  [(size_t)kM * kC];
__device__ float  g_c  [(size_t)kM * kC];
__device__ __half g_w  [786432];

__device__ __forceinline__ int win_to_nat(int m) {
    int win = m >> 6;
    int t   = m & 63;
    int b   = win >> 8;
    int wi  = win & 255;
    int row = ((wi >> 4) << 3) + (t >> 3);
    int col = ((wi & 15) << 3) + (t & 7);
    return b * kNtok + row * kGrid + col;
}

__device__ __forceinline__ float gelu_exact(float x) {
    return 0.5f * x * (1.0f + erff(x * 0.70710678118654752f));
}

__device__ __forceinline__ void cpa16(__half* s, const __half* g) {
    uint32_t sa = (uint32_t)__cvta_generic_to_shared(s);
    asm volatile("cp.async.cg.shared.global [%0], [%1], 16;" :: "r"(sa), "l"(g));
}

__device__ __forceinline__ void mma16816(float* c, uint32_t a0, uint32_t a1,
                                         uint32_t a2, uint32_t a3,
                                         uint32_t b0, uint32_t b1) {
    asm volatile(
        "mma.sync.aligned.m16n8k16.row.col.f32.f16.f16.f32 "
        "{%0,%1,%2,%3}, {%4,%5,%6,%7}, {%8,%9}, {%0,%1,%2,%3};"
        : "+f"(c[0]), "+f"(c[1]), "+f"(c[2]), "+f"(c[3])
        : "r"(a0), "r"(a1), "r"(a2), "r"(a3), "r"(b0), "r"(b1));
}

__device__ __forceinline__ uint32_t packh2(float x, float y) {
    __half2 h = __floats2half2_rn(x, y);
    return *(uint32_t*)&h;
}

// ---------------- fp16 weight conversion (single launch) ----------------
__global__ __launch_bounds__(256) void cvtw_all(
    const float* __restrict__ in_w, const float* __restrict__ out_w,
    const float* __restrict__ w1, const float* __restrict__ w2,
    __half* __restrict__ o)
{
    int i = blockIdx.x * 256 + threadIdx.x;
    const float* src;
    int off;
    if (i < 196608)      { src = in_w;  off = i; }
    else if (i < 262144) { src = out_w; off = i - 196608; }
    else if (i < 524288) { src = w1;    off = i - 262144; }
    else                 { src = w2;    off = i - 524288; }
    o[i] = __float2half(src[off]);
}

// ---------------- LayerNorm: one warp per row, fp32 in, fp16 out ----------
template <bool REMAP_IN>
__global__ __launch_bounds__(256) void ln_kernel(
    const float* __restrict__ in, const float* __restrict__ g,
    const float* __restrict__ b, __half* __restrict__ out)
{
    int row  = blockIdx.x * 8 + (threadIdx.x >> 5);
    int lane = threadIdx.x & 31;
    int src  = REMAP_IN ? win_to_nat(row) : row;

    const float4* p = (const float4*)(in + (size_t)src * kC);
    float4 v0 = p[lane];
    float4 v1 = p[lane + 32];

    float s  = v0.x + v0.y + v0.z + v0.w + v1.x + v1.y + v1.z + v1.w;
    float s2 = v0.x*v0.x + v0.y*v0.y + v0.z*v0.z + v0.w*v0.w
             + v1.x*v1.x + v1.y*v1.y + v1.z*v1.z + v1.w*v1.w;
    #pragma unroll
    for (int off = 16; off > 0; off >>= 1) {
        s  += __shfl_xor_sync(0xffffffffu, s,  off);
        s2 += __shfl_xor_sync(0xffffffffu, s2, off);
    }
    float mean = s * (1.0f / kC);
    float var  = s2 * (1.0f / kC) - mean * mean;
    float inv  = rsqrtf(var + 1e-5f);

    const float4* gp = (const float4*)g;
    const float4* bp = (const float4*)b;
    float4 g0 = gp[lane], g1 = gp[lane + 32];
    float4 b0 = bp[lane], b1 = bp[lane + 32];

    __half2 h0 = __floats2half2_rn((v0.x - mean) * inv * g0.x + b0.x,
                                   (v0.y - mean) * inv * g0.y + b0.y);
    __half2 h1 = __floats2half2_rn((v0.z - mean) * inv * g0.z + b0.z,
                                   (v0.w - mean) * inv * g0.w + b0.w);
    __half2 h2 = __floats2half2_rn((v1.x - mean) * inv * g1.x + b1.x,
                                   (v1.y - mean) * inv * g1.y + b1.y);
    __half2 h3 = __floats2half2_rn((v1.z - mean) * inv * g1.z + b1.z,
                                   (v1.w - mean) * inv * g1.w + b1.w);

    __half2* q = (__half2*)(out + (size_t)row * kC);
    q[lane * 2]          = h0;
    q[lane * 2 + 1]      = h1;
    q[64 + lane * 2]     = h2;
    q[64 + lane * 2 + 1] = h3;
}

// ---------------- fp16 tensor-core GEMM (unchanged from round 4) ----------
constexpr int kStrH = 48;

template <int EPI>
__global__ __launch_bounds__(256) void hgemm_kernel(
    const __half* __restrict__ A, const __half* __restrict__ W,
    const float* __restrict__ bias, const float* __restrict__ res,
    void* __restrict__ out_v, int M, int N, int K)
{
    __shared__ __half As[2][128 * kStrH];
    __shared__ __half Bs[2][128 * kStrH];

    const int bm   = blockIdx.y * 128;
    const int bn   = blockIdx.x * 128;
    const int tid  = threadIdx.x;
    const int warp = tid >> 5;
    const int lane = tid & 31;
    const int grp  = lane >> 2;
    const int tig  = lane & 3;
    const int wm   = warp & 1;
    const int wn   = warp >> 1;

    const __half* Ag = A + (size_t)bm * K;
    const __half* Wg = W + (size_t)bn * K;

    float c[4][4][4];
    #pragma unroll
    for (int i = 0; i < 4; i++)
        #pragma unroll
        for (int j = 0; j < 4; j++)
            #pragma unroll
            for (int r = 0; r < 4; r++) c[i][j][r] = 0.0f;

    const int T = K >> 5;

    #pragma unroll
    for (int u = 0; u < 2; u++) {
        int idx = tid + u * 256;
        int row = idx >> 2;
        int ch  = idx & 3;
        cpa16(&As[0][row * kStrH + ch * 8], Ag + (size_t)row * K + ch * 8);
        cpa16(&Bs[0][row * kStrH + ch * 8], Wg + (size_t)row * K + ch * 8);
    }
    asm volatile("cp.async.commit_group;");

    for (int t = 0; t < T; t++) {
        if (t + 1 < T) {
            int k0  = (t + 1) << 5;
            int buf = (t + 1) & 1;
            #pragma unroll
            for (int u = 0; u < 2; u++) {
                int idx = tid + u * 256;
                int row = idx >> 2;
                int ch  = idx & 3;
                cpa16(&As[buf][row * kStrH + ch * 8], Ag + (size_t)row * K + k0 + ch * 8);
                cpa16(&Bs[buf][row * kStrH + ch * 8], Wg + (size_t)row * K + k0 + ch * 8);
            }
            asm volatile("cp.async.commit_group;");
            asm volatile("cp.async.wait_group 1;");
        } else {
            asm volatile("cp.async.wait_group 0;");
        }
        __syncthreads();

        const __half* as = As[t & 1];
        const __half* bs = Bs[t & 1];

        #pragma unroll
        for (int kb = 0; kb < 2; kb++) {
            uint32_t af[4][4];
            uint32_t bf[4][2];
            const int kcol = kb * 16 + tig * 4;
            #pragma unroll
            for (int i = 0; i < 4; i++) {
                int r = wm * 64 + i * 16 + grp;
                uint2 lo = *(const uint2*)&as[r * kStrH + kcol];
                uint2 hi = *(const uint2*)&as[(r + 8) * kStrH + kcol];
                af[i][0] = lo.x; af[i][1] = hi.x;
                af[i][2] = lo.y; af[i][3] = hi.y;
            }
            #pragma unroll
            for (int j = 0; j < 4; j++) {
                int n = wn * 32 + j * 8 + grp;
                uint2 bv = *(const uint2*)&bs[n * kStrH + kcol];
                bf[j][0] = bv.x; bf[j][1] = bv.y;
            }
            #pragma unroll
            for (int i = 0; i < 4; i++)
                #pragma unroll
                for (int j = 0; j < 4; j++)
                    mma16816(c[i][j], af[i][0], af[i][1], af[i][2], af[i][3],
                             bf[j][0], bf[j][1]);
        }
        __syncthreads();
    }

    #pragma unroll
    for (int i = 0; i < 4; i++) {
        int mrow0 = bm + wm * 64 + i * 16 + grp;
        int mrow1 = mrow0 + 8;
        int or0 = (EPI == 2) ? win_to_nat(mrow0) : mrow0;
        int or1 = (EPI == 2) ? win_to_nat(mrow1) : mrow1;
        #pragma unroll
        for (int j = 0; j < 4; j++) {
            int col = bn + wn * 32 + j * 8 + 2 * tig;
            float2 bv = *(const float2*)&bias[col];
            float v0 = c[i][j][0] + bv.x;
            float v1 = c[i][j][1] + bv.y;
            float v2 = c[i][j][2] + bv.x;
            float v3 = c[i][j][3] + bv.y;
            if (EPI == 0) {
                __half* out = (__half*)out_v;
                *(__half2*)&out[(size_t)or0 * N + col] = __floats2half2_rn(v0, v1);
                *(__half2*)&out[(size_t)or1 * N + col] = __floats2half2_rn(v2, v3);
            } else if (EPI == 1) {
                __half* out = (__half*)out_v;
                *(__half2*)&out[(size_t)or0 * N + col] =
                    __floats2half2_rn(gelu_exact(v0), gelu_exact(v1));
                *(__half2*)&out[(size_t)or1 * N + col] =
                    __floats2half2_rn(gelu_exact(v2), gelu_exact(v3));
            } else {
                float* out = (float*)out_v;
                float2 r0 = *(const float2*)&res[(size_t)or0 * 256 + col];
                float2 r1 = *(const float2*)&res[(size_t)or1 * 256 + col];
                *(float2*)&out[(size_t)or0 * N + col] = make_float2(v0 + r0.x, v1 + r0.y);
                *(float2*)&out[(size_t)or1 * N + col] = make_float2(v2 + r1.x, v3 + r1.y);
            }
        }
    }
}

// ---------------- mma window attention: 1 CTA per window, 1 warp per head --
constexpr int kQKstr = 272;                        // halves per Q/K smem row
constexpr int kVTstr = 72;                         // halves per V^T smem row
constexpr int kQoff  = 0;
constexpr int kKoff  = 64 * kQKstr;                // 17408
constexpr int kVoff  = 2 * 64 * kQKstr;            // 34816
constexpr int kAttnSmem = (2 * 64 * kQKstr + 8 * 32 * kVTstr) * 2;  // 106496 B

__global__ __launch_bounds__(256) void attn_mma_kernel(
    const __half* __restrict__ qkv, __half* __restrict__ o)
{
    extern __shared__ __half sm[];
    const int tid  = threadIdx.x;
    const int win  = blockIdx.x;
    const int h    = tid >> 5;     // warp = head
    const int lane = tid & 31;
    const int grp  = lane >> 2;
    const int tig  = lane & 3;

    // ---- stage Q, K row-major; V transposed per head ----
    const __half* gbase = qkv + (size_t)win * 64 * 768;
    for (int idx = tid; idx < 2048; idx += 256) {
        int t  = idx >> 5;
        int c8 = (idx & 31) << 3;
        const __half* gp = gbase + t * 768 + c8;
        *(uint4*)&sm[kQoff + t * kQKstr + c8] = *(const uint4*)gp;
        *(uint4*)&sm[kKoff + t * kQKstr + c8] = *(const uint4*)(gp + 256);
        uint4 vv = *(const uint4*)(gp + 512);
        __half vh[8];
        *(uint4*)vh = vv;
        int hh = c8 >> 5;
        int dl = c8 & 31;
        #pragma unroll
        for (int r = 0; r < 8; r++)
            sm[kVoff + hh * (32 * kVTstr) + (dl + r) * kVTstr + t] = vh[r];
    }
    __syncthreads();

    // ---- per m-tile: QK^T (64 cols), softmax, pack prob fragments ----
    const float scale = 0.17677669529663687f;  // 1/sqrt(32)
    uint32_t ph0[4][8], ph1[4][8];

    #pragma unroll
    for (int i = 0; i < 4; i++) {
        float s[8][4];
        #pragma unroll
        for (int j = 0; j < 8; j++)
            #pragma unroll
            for (int r = 0; r < 4; r++) s[j][r] = 0.0f;

        #pragma unroll
        for (int kb = 0; kb < 2; kb++) {
            const int kcol = h * 32 + kb * 16 + tig * 4;
            const int r = i * 16 + grp;
            uint2 qlo = *(const uint2*)&sm[kQoff + r * kQKstr + kcol];
            uint2 qhi = *(const uint2*)&sm[kQoff + (r + 8) * kQKstr + kcol];
            #pragma unroll
            for (int j = 0; j < 8; j++) {
                uint2 kv = *(const uint2*)&sm[kKoff + (j * 8 + grp) * kQKstr + kcol];
                mma16816(s[j], qlo.x, qhi.x, qlo.y, qhi.y, kv.x, kv.y);
            }
        }

        // softmax: row0 = grp (+16i), row1 = grp+8 (+16i)
        float mx0 = -1e30f, mx1 = -1e30f;
        #pragma unroll
        for (int j = 0; j < 8; j++) {
            mx0 = fmaxf(mx0, fmaxf(s[j][0], s[j][1]));
            mx1 = fmaxf(mx1, fmaxf(s[j][2], s[j][3]));
        }
        mx0 = fmaxf(mx0, __shfl_xor_sync(0xffffffffu, mx0, 1));
        mx0 = fmaxf(mx0, __shfl_xor_sync(0xffffffffu, mx0, 2));
        mx1 = fmaxf(mx1, __shfl_xor_sync(0xffffffffu, mx1, 1));
        mx1 = fmaxf(mx1, __shfl_xor_sync(0xffffffffu, mx1, 2));

        float sum0 = 0.0f, sum1 = 0.0f;
        #pragma unroll
        for (int j = 0; j < 8; j++) {
            s[j][0] = __expf((s[j][0] - mx0) * scale);
            s[j][1] = __expf((s[j][1] - mx0) * scale);
            s[j][2] = __expf((s[j][2] - mx1) * scale);
            s[j][3] = __expf((s[j][3] - mx1) * scale);
            sum0 += s[j][0] + s[j][1];
            sum1 += s[j][2] + s[j][3];
        }
        sum0 += __shfl_xor_sync(0xffffffffu, sum0, 1);
        sum0 += __shfl_xor_sync(0xffffffffu, sum0, 2);
        sum1 += __shfl_xor_sync(0xffffffffu, sum1, 1);
        sum1 += __shfl_xor_sync(0xffffffffu, sum1, 2);
        float inv0 = 1.0f / sum0;
        float inv1 = 1.0f / sum1;

        #pragma unroll
        for (int j = 0; j < 8; j++) {
            ph0[i][j] = packh2(s[j][0] * inv0, s[j][1] * inv0);
            ph1[i][j] = packh2(s[j][2] * inv1, s[j][3] * inv1);
        }
    }

    // ---- AV: O[64][32] = att[64][64] @ V[64][32] ----
    float oa[4][4][4];
    #pragma unroll
    for (int i = 0; i < 4; i++)
        #pragma unroll
        for (int j = 0; j < 4; j++)
            #pragma unroll
            for (int r = 0; r < 4; r++) oa[i][j][r] = 0.0f;

    #pragma unroll
    for (int kk = 0; kk < 4; kk++) {
        uint32_t bf0[4], bf1[4];
        #pragma unroll
        for (int jn = 0; jn < 4; jn++) {
            const __half* vp = &sm[kVoff + h * (32 * kVTstr) + (jn * 8 + grp) * kVTstr
                                   + kk * 16 + tig * 2];
            bf0[jn] = *(const uint32_t*)vp;
            bf1[jn] = *(const uint32_t*)(vp + 8);
        }
        #pragma unroll
        for (int i = 0; i < 4; i++)
            #pragma unroll
            for (int jn = 0; jn < 4; jn++)
                mma16816(oa[i][jn], ph0[i][2 * kk], ph1[i][2 * kk],
                         ph0[i][2 * kk + 1], ph1[i][2 * kk + 1],
                         bf0[jn], bf1[jn]);
    }

    // ---- store O ----
    #pragma unroll
    for (int i = 0; i < 4; i++) {
        int gr = win * 64 + i * 16 + grp;
        #pragma unroll
        for (int jn = 0; jn < 4; jn++) {
            int col = h * 32 + jn * 8 + tig * 2;
            *(__half2*)&o[(size_t)gr * 256 + col] =
                __floats2half2_rn(oa[i][jn][0], oa[i][jn][1]);
            *(__half2*)&o[(size_t)(gr + 8) * 256 + col] =
                __floats2half2_rn(oa[i][jn][2], oa[i][jn][3]);
        }
    }
}

// ---------------- launch ----------------
extern "C" void kernel_launch(void* const* d_in, const int* in_sizes, int n_in,
                              void* d_out, int out_size)
{
    const float* x     = (const float*)d_in[0];
    const float* ln1_g = (const float*)d_in[1];
    const float* ln1_b = (const float*)d_in[2];
    const float* in_w  = (const float*)d_in[3];
    const float* in_b  = (const float*)d_in[4];
    const float* out_w = (const float*)d_in[5];
    const float* out_b = (const float*)d_in[6];
    const float* ln2_g = (const float*)d_in[7];
    const float* ln2_b = (const float*)d_in[8];
    const float* w1    = (const float*)d_in[9];
    const float* b1    = (const float*)d_in[10];
    const float* w2    = (const float*)d_in[11];
    const float* b2    = (const float*)d_in[12];
    float* out = (float*)d_out;

    __half *big, *a, *bb, *w;
    float *cc;
    cudaGetSymbolAddress((void**)&big, g_big);
    cudaGetSymbolAddress((void**)&a,   g_a);
    cudaGetSymbolAddress((void**)&bb,  g_b);
    cudaGetSymbolAddress((void**)&cc,  g_c);
    cudaGetSymbolAddress((void**)&w,   g_w);

    __half* w_in  = w;
    __half* w_out = w + 196608;
    __half* w_1   = w + 262144;
    __half* w_2   = w + 524288;

    cudaFuncSetAttribute(attn_mma_kernel,
                         cudaFuncAttributeMaxDynamicSharedMemorySize, kAttnSmem);

    // 0) fp16 weights (single launch)
    cvtw_all<<<3072, 256>>>(in_w, out_w, w1, w2, w);
    // 1) LN1, natural -> windowed order, half out
    ln_kernel<true><<<kM / 8, 256>>>(x, ln1_g, ln1_b, a);
    // 2) QKV projection
    hgemm_kernel<0><<<dim3(6, kM / 128), 256>>>(a, w_in, in_b, nullptr, big, kM, 768, kC);
    // 3) windowed attention (tensor-core)
    attn_mma_kernel<<<kNWin, 256, kAttnSmem>>>(big, bb);
    // 4) out-proj + window-reverse + residual -> fp32 x2
    hgemm_kernel<2><<<dim3(2, kM / 128), 256>>>(bb, w_out, out_b, x, cc, kM, kC, kC);
    // 5) LN2, half out
    ln_kernel<false><<<kM / 8, 256>>>(cc, ln2_g, ln2_b, a);
    // 6) MLP up + exact GELU
    hgemm_kernel<1><<<dim3(8, kM / 128), 256>>>(a, w_1, b1, nullptr, big, kM, kHid, kC);
    // 7) MLP down + residual -> fp32 final output
    hgemm_kernel<3><<<dim3(2, kM / 128), 256>>>(big, w_2, b2, cc, out, kM, kC, kHid);
}

// round 6
// speedup vs baseline: 5.1341x; 1.1119x over previous
#include <cuda_runtime.h>
#include <cuda_fp16.h>
#include <cstdint>
#include <math.h>

// ---------------- problem constants ----------------
constexpr int kB    = 8;
constexpr int kGrid = 128;
constexpr int kNtok = kGrid * kGrid;
constexpr int kC    = 256;
constexpr int kM    = kB * kNtok;     // 131072 tokens
constexpr int kHid  = 1024;
constexpr int kNWin = kB * 256;       // 2048 windows

// ---------------- scratch ----------------
__device__ __half g_big[(size_t)kM * kHid];
__device__ __half g_a  [(size_t)kM * kC];
__device__ __half g_b  [(size_t)kM * kC];
__device__ float  g_c  [(size_t)kM * kC];
__device__ __half g_w  [786432];

__device__ __forceinline__ int win_to_nat(int m) {
    int win = m >> 6;
    int t   = m & 63;
    int b   = win >> 8;
    int wi  = win & 255;
    int row = ((wi >> 4) << 3) + (t >> 3);
    int col = ((wi & 15) << 3) + (t & 7);
    return b * kNtok + row * kGrid + col;
}

__device__ __forceinline__ float gelu_exact(float x) {
    return 0.5f * x * (1.0f + erff(x * 0.70710678118654752f));
}

__device__ __forceinline__ void cpa16(__half* s, const __half* g) {
    uint32_t sa = (uint32_t)__cvta_generic_to_shared(s);
    asm volatile("cp.async.cg.shared.global [%0], [%1], 16;" :: "r"(sa), "l"(g));
}

__device__ __forceinline__ void mma16816(float* c, uint32_t a0, uint32_t a1,
                                         uint32_t a2, uint32_t a3,
                                         uint32_t b0, uint32_t b1) {
    asm volatile(
        "mma.sync.aligned.m16n8k16.row.col.f32.f16.f16.f32 "
        "{%0,%1,%2,%3}, {%4,%5,%6,%7}, {%8,%9}, {%0,%1,%2,%3};"
        : "+f"(c[0]), "+f"(c[1]), "+f"(c[2]), "+f"(c[3])
        : "r"(a0), "r"(a1), "r"(a2), "r"(a3), "r"(b0), "r"(b1));
}

__device__ __forceinline__ void ldsm4t(uint32_t* r, uint32_t addr) {
    asm volatile("ldmatrix.sync.aligned.m8n8.x4.trans.shared.b16 {%0,%1,%2,%3}, [%4];"
        : "=r"(r[0]), "=r"(r[1]), "=r"(r[2]), "=r"(r[3]) : "r"(addr));
}

__device__ __forceinline__ uint32_t packh2(float x, float y) {
    __half2 h = __floats2half2_rn(x, y);
    return *(uint32_t*)&h;
}

// ---------------- fp16 weight conversion (single launch) ----------------
__global__ __launch_bounds__(256) void cvtw_all(
    const float* __restrict__ in_w, const float* __restrict__ out_w,
    const float* __restrict__ w1, const float* __restrict__ w2,
    __half* __restrict__ o)
{
    int i = blockIdx.x * 256 + threadIdx.x;
    const float* src;
    int off;
    if (i < 196608)      { src = in_w;  off = i; }
    else if (i < 262144) { src = out_w; off = i - 196608; }
    else if (i < 524288) { src = w1;    off = i - 262144; }
    else                 { src = w2;    off = i - 524288; }
    o[i] = __float2half(src[off]);
}

// ---------------- LayerNorm: one warp per row, fp32 in, fp16 out ----------
template <bool REMAP_IN>
__global__ __launch_bounds__(256) void ln_kernel(
    const float* __restrict__ in, const float* __restrict__ g,
    const float* __restrict__ b, __half* __restrict__ out)
{
    int row  = blockIdx.x * 8 + (threadIdx.x >> 5);
    int lane = threadIdx.x & 31;
    int src  = REMAP_IN ? win_to_nat(row) : row;

    const float4* p = (const float4*)(in + (size_t)src * kC);
    float4 v0 = p[lane];
    float4 v1 = p[lane + 32];

    float s  = v0.x + v0.y + v0.z + v0.w + v1.x + v1.y + v1.z + v1.w;
    float s2 = v0.x*v0.x + v0.y*v0.y + v0.z*v0.z + v0.w*v0.w
             + v1.x*v1.x + v1.y*v1.y + v1.z*v1.z + v1.w*v1.w;
    #pragma unroll
    for (int off = 16; off > 0; off >>= 1) {
        s  += __shfl_xor_sync(0xffffffffu, s,  off);
        s2 += __shfl_xor_sync(0xffffffffu, s2, off);
    }
    float mean = s * (1.0f / kC);
    float var  = s2 * (1.0f / kC) - mean * mean;
    float inv  = rsqrtf(var + 1e-5f);

    const float4* gp = (const float4*)g;
    const float4* bp = (const float4*)b;
    float4 g0 = gp[lane], g1 = gp[lane + 32];
    float4 b0 = bp[lane], b1 = bp[lane + 32];

    __half2 h0 = __floats2half2_rn((v0.x - mean) * inv * g0.x + b0.x,
                                   (v0.y - mean) * inv * g0.y + b0.y);
    __half2 h1 = __floats2half2_rn((v0.z - mean) * inv * g0.z + b0.z,
                                   (v0.w - mean) * inv * g0.w + b0.w);
    __half2 h2 = __floats2half2_rn((v1.x - mean) * inv * g1.x + b1.x,
                                   (v1.y - mean) * inv * g1.y + b1.y);
    __half2 h3 = __floats2half2_rn((v1.z - mean) * inv * g1.z + b1.z,
                                   (v1.w - mean) * inv * g1.w + b1.w);

    __half2* q = (__half2*)(out + (size_t)row * kC);
    q[lane * 2]          = h0;
    q[lane * 2 + 1]      = h1;
    q[64 + lane * 2]     = h2;
    q[64 + lane * 2 + 1] = h3;
}

// ---------------- fp16 tensor-core GEMM (unchanged) ----------
constexpr int kStrH = 48;

template <int EPI>
__global__ __launch_bounds__(256) void hgemm_kernel(
    const __half* __restrict__ A, const __half* __restrict__ W,
    const float* __restrict__ bias, const float* __restrict__ res,
    void* __restrict__ out_v, int M, int N, int K)
{
    __shared__ __half As[2][128 * kStrH];
    __shared__ __half Bs[2][128 * kStrH];

    const int bm   = blockIdx.y * 128;
    const int bn   = blockIdx.x * 128;
    const int tid  = threadIdx.x;
    const int warp = tid >> 5;
    const int lane = tid & 31;
    const int grp  = lane >> 2;
    const int tig  = lane & 3;
    const int wm   = warp & 1;
    const int wn   = warp >> 1;

    const __half* Ag = A + (size_t)bm * K;
    const __half* Wg = W + (size_t)bn * K;

    float c[4][4][4];
    #pragma unroll
    for (int i = 0; i < 4; i++)
        #pragma unroll
        for (int j = 0; j < 4; j++)
            #pragma unroll
            for (int r = 0; r < 4; r++) c[i][j][r] = 0.0f;

    const int T = K >> 5;

    #pragma unroll
    for (int u = 0; u < 2; u++) {
        int idx = tid + u * 256;
        int row = idx >> 2;
        int ch  = idx & 3;
        cpa16(&As[0][row * kStrH + ch * 8], Ag + (size_t)row * K + ch * 8);
        cpa16(&Bs[0][row * kStrH + ch * 8], Wg + (size_t)row * K + ch * 8);
    }
    asm volatile("cp.async.commit_group;");

    for (int t = 0; t < T; t++) {
        if (t + 1 < T) {
            int k0  = (t + 1) << 5;
            int buf = (t + 1) & 1;
            #pragma unroll
            for (int u = 0; u < 2; u++) {
                int idx = tid + u * 256;
                int row = idx >> 2;
                int ch  = idx & 3;
                cpa16(&As[buf][row * kStrH + ch * 8], Ag + (size_t)row * K + k0 + ch * 8);
                cpa16(&Bs[buf][row * kStrH + ch * 8], Wg + (size_t)row * K + k0 + ch * 8);
            }
            asm volatile("cp.async.commit_group;");
            asm volatile("cp.async.wait_group 1;");
        } else {
            asm volatile("cp.async.wait_group 0;");
        }
        __syncthreads();

        const __half* as = As[t & 1];
        const __half* bs = Bs[t & 1];

        #pragma unroll
        for (int kb = 0; kb < 2; kb++) {
            uint32_t af[4][4];
            uint32_t bf[4][2];
            const int kcol = kb * 16 + tig * 4;
            #pragma unroll
            for (int i = 0; i < 4; i++) {
                int r = wm * 64 + i * 16 + grp;
                uint2 lo = *(const uint2*)&as[r * kStrH + kcol];
                uint2 hi = *(const uint2*)&as[(r + 8) * kStrH + kcol];
                af[i][0] = lo.x; af[i][1] = hi.x;
                af[i][2] = lo.y; af[i][3] = hi.y;
            }
            #pragma unroll
            for (int j = 0; j < 4; j++) {
                int n = wn * 32 + j * 8 + grp;
                uint2 bv = *(const uint2*)&bs[n * kStrH + kcol];
                bf[j][0] = bv.x; bf[j][1] = bv.y;
            }
            #pragma unroll
            for (int i = 0; i < 4; i++)
                #pragma unroll
                for (int j = 0; j < 4; j++)
                    mma16816(c[i][j], af[i][0], af[i][1], af[i][2], af[i][3],
                             bf[j][0], bf[j][1]);
        }
        __syncthreads();
    }

    #pragma unroll
    for (int i = 0; i < 4; i++) {
        int mrow0 = bm + wm * 64 + i * 16 + grp;
        int mrow1 = mrow0 + 8;
        int or0 = (EPI == 2) ? win_to_nat(mrow0) : mrow0;
        int or1 = (EPI == 2) ? win_to_nat(mrow1) : mrow1;
        #pragma unroll
        for (int j = 0; j < 4; j++) {
            int col = bn + wn * 32 + j * 8 + 2 * tig;
            float2 bv = *(const float2*)&bias[col];
            float v0 = c[i][j][0] + bv.x;
            float v1 = c[i][j][1] + bv.y;
            float v2 = c[i][j][2] + bv.x;
            float v3 = c[i][j][3] + bv.y;
            if (EPI == 0) {
                __half* out = (__half*)out_v;
                *(__half2*)&out[(size_t)or0 * N + col] = __floats2half2_rn(v0, v1);
                *(__half2*)&out[(size_t)or1 * N + col] = __floats2half2_rn(v2, v3);
            } else if (EPI == 1) {
                __half* out = (__half*)out_v;
                *(__half2*)&out[(size_t)or0 * N + col] =
                    __floats2half2_rn(gelu_exact(v0), gelu_exact(v1));
                *(__half2*)&out[(size_t)or1 * N + col] =
                    __floats2half2_rn(gelu_exact(v2), gelu_exact(v3));
            } else {
                float* out = (float*)out_v;
                float2 r0 = *(const float2*)&res[(size_t)or0 * 256 + col];
                float2 r1 = *(const float2*)&res[(size_t)or1 * 256 + col];
                *(float2*)&out[(size_t)or0 * N + col] = make_float2(v0 + r0.x, v1 + r0.y);
                *(float2*)&out[(size_t)or1 * N + col] = make_float2(v2 + r1.x, v3 + r1.y);
            }
        }
    }
}

// ---------------- mma window attention v2: 1 CTA/window, warp=head --------
// V staged row-major, AV B-fragments via ldmatrix.trans (no transpose stores).
constexpr int kQKstr = 272;                 // halves per Q/K smem row
constexpr int kVstr  = 264;                 // halves per V smem row
constexpr int kQoff  = 0;
constexpr int kKoff  = 64 * kQKstr;         // 17408
constexpr int kVoff  = 2 * 64 * kQKstr;     // 34816
constexpr int kAttnSmem = (kVoff + 64 * kVstr) * 2;  // 103424 B

__global__ __launch_bounds__(256, 2) void attn_mma_kernel(
    const __half* __restrict__ qkv, __half* __restrict__ o)
{
    extern __shared__ __half sm[];
    const int tid  = threadIdx.x;
    const int win  = blockIdx.x;
    const int h    = tid >> 5;     // warp = head
    const int lane = tid & 31;
    const int grp  = lane >> 2;
    const int tig  = lane & 3;

    // ---- stage Q, K, V row-major (all uint4, conflict-free) ----
    const __half* gbase = qkv + (size_t)win * 64 * 768;
    #pragma unroll
    for (int u = 0; u < 8; u++) {
        int idx = tid + u * 256;
        int t   = idx >> 5;
        int c8  = (idx & 31) << 3;
        const __half* gp = gbase + t * 768 + c8;
        *(uint4*)&sm[kQoff + t * kQKstr + c8] = *(const uint4*)gp;
        *(uint4*)&sm[kKoff + t * kQKstr + c8] = *(const uint4*)(gp + 256);
        *(uint4*)&sm[kVoff + t * kVstr  + c8] = *(const uint4*)(gp + 512);
    }
    __syncthreads();

    // ---- V fragments for this head via ldmatrix.x4.trans (resident) ----
    uint32_t bf[4][4][2];
    {
        const uint32_t smb = (uint32_t)__cvta_generic_to_shared(sm);
        int srow = (lane & 7) + ((lane >> 3) & 1) * 8;
        int dcol = h * 32 + (lane >> 4) * 8;
        #pragma unroll
        for (int kk = 0; kk < 4; kk++) {
            #pragma unroll
            for (int jp = 0; jp < 2; jp++) {
                uint32_t addr = smb +
                    (uint32_t)(kVoff + (kk * 16 + srow) * kVstr + dcol + jp * 16) * 2;
                uint32_t r[4];
                ldsm4t(r, addr);
                bf[kk][jp * 2 + 0][0] = r[0];
                bf[kk][jp * 2 + 0][1] = r[1];
                bf[kk][jp * 2 + 1][0] = r[2];
                bf[kk][jp * 2 + 1][1] = r[3];
            }
        }
    }

    const float scale = 0.17677669529663687f;  // 1/sqrt(32)

    // ---- stream m-tiles: QK^T -> softmax -> AV -> store ----
    #pragma unroll
    for (int i = 0; i < 4; i++) {
        float s[8][4];
        #pragma unroll
        for (int j = 0; j < 8; j++)
            #pragma unroll
            for (int r = 0; r < 4; r++) s[j][r] = 0.0f;

        #pragma unroll
        for (int kb = 0; kb < 2; kb++) {
            const int kcol = h * 32 + kb * 16 + tig * 4;
            const int r = i * 16 + grp;
            uint2 qlo = *(const uint2*)&sm[kQoff + r * kQKstr + kcol];
            uint2 qhi = *(const uint2*)&sm[kQoff + (r + 8) * kQKstr + kcol];
            #pragma unroll
            for (int j = 0; j < 8; j++) {
                uint2 kv = *(const uint2*)&sm[kKoff + (j * 8 + grp) * kQKstr + kcol];
                mma16816(s[j], qlo.x, qhi.x, qlo.y, qhi.y, kv.x, kv.y);
            }
        }

        float mx0 = -1e30f, mx1 = -1e30f;
        #pragma unroll
        for (int j = 0; j < 8; j++) {
            mx0 = fmaxf(mx0, fmaxf(s[j][0], s[j][1]));
            mx1 = fmaxf(mx1, fmaxf(s[j][2], s[j][3]));
        }
        mx0 = fmaxf(mx0, __shfl_xor_sync(0xffffffffu, mx0, 1));
        mx0 = fmaxf(mx0, __shfl_xor_sync(0xffffffffu, mx0, 2));
        mx1 = fmaxf(mx1, __shfl_xor_sync(0xffffffffu, mx1, 1));
        mx1 = fmaxf(mx1, __shfl_xor_sync(0xffffffffu, mx1, 2));

        float sum0 = 0.0f, sum1 = 0.0f;
        #pragma unroll
        for (int j = 0; j < 8; j++) {
            s[j][0] = __expf((s[j][0] - mx0) * scale);
            s[j][1] = __expf((s[j][1] - mx0) * scale);
            s[j][2] = __expf((s[j][2] - mx1) * scale);
            s[j][3] = __expf((s[j][3] - mx1) * scale);
            sum0 += s[j][0] + s[j][1];
            sum1 += s[j][2] + s[j][3];
        }
        sum0 += __shfl_xor_sync(0xffffffffu, sum0, 1);
        sum0 += __shfl_xor_sync(0xffffffffu, sum0, 2);
        sum1 += __shfl_xor_sync(0xffffffffu, sum1, 1);
        sum1 += __shfl_xor_sync(0xffffffffu, sum1, 2);
        float inv0 = 1.0f / sum0;
        float inv1 = 1.0f / sum1;

        uint32_t ph0[8], ph1[8];
        #pragma unroll
        for (int j = 0; j < 8; j++) {
            ph0[j] = packh2(s[j][0] * inv0, s[j][1] * inv0);
            ph1[j] = packh2(s[j][2] * inv1, s[j][3] * inv1);
        }

        float oa[4][4];
        #pragma unroll
        for (int jn = 0; jn < 4; jn++)
            #pragma unroll
            for (int r = 0; r < 4; r++) oa[jn][r] = 0.0f;

        #pragma unroll
        for (int kk = 0; kk < 4; kk++)
            #pragma unroll
            for (int jn = 0; jn < 4; jn++)
                mma16816(oa[jn], ph0[2 * kk], ph1[2 * kk],
                         ph0[2 * kk + 1], ph1[2 * kk + 1],
                         bf[kk][jn][0], bf[kk][jn][1]);

        int gr = win * 64 + i * 16 + grp;
        #pragma unroll
        for (int jn = 0; jn < 4; jn++) {
            int col = h * 32 + jn * 8 + tig * 2;
            *(__half2*)&o[(size_t)gr * 256 + col] =
                __floats2half2_rn(oa[jn][0], oa[jn][1]);
            *(__half2*)&o[(size_t)(gr + 8) * 256 + col] =
                __floats2half2_rn(oa[jn][2], oa[jn][3]);
        }
    }
}

// ---------------- launch ----------------
extern "C" void kernel_launch(void* const* d_in, const int* in_sizes, int n_in,
                              void* d_out, int out_size)
{
    const float* x     = (const float*)d_in[0];
    const float* ln1_g = (const float*)d_in[1];
    const float* ln1_b = (const float*)d_in[2];
    const float* in_w  = (const float*)d_in[3];
    const float* in_b  = (const float*)d_in[4];
    const float* out_w = (const float*)d_in[5];
    const float* out_b = (const float*)d_in[6];
    const float* ln2_g = (const float*)d_in[7];
    const float* ln2_b = (const float*)d_in[8];
    const float* w1    = (const float*)d_in[9];
    const float* b1    = (const float*)d_in[10];
    const float* w2    = (const float*)d_in[11];
    const float* b2    = (const float*)d_in[12];
    float* out = (float*)d_out;

    __half *big, *a, *bb, *w;
    float *cc;
    cudaGetSymbolAddress((void**)&big, g_big);
    cudaGetSymbolAddress((void**)&a,   g_a);
    cudaGetSymbolAddress((void**)&bb,  g_b);
    cudaGetSymbolAddress((void**)&cc,  g_c);
    cudaGetSymbolAddress((void**)&w,   g_w);

    __half* w_in  = w;
    __half* w_out = w + 196608;
    __half* w_1   = w + 262144;
    __half* w_2   = w + 524288;

    cudaFuncSetAttribute(attn_mma_kernel,
                         cudaFuncAttributeMaxDynamicSharedMemorySize, kAttnSmem);

    // 0) fp16 weights (single launch)
    cvtw_all<<<3072, 256>>>(in_w, out_w, w1, w2, w);
    // 1) LN1, natural -> windowed order, half out
    ln_kernel<true><<<kM / 8, 256>>>(x, ln1_g, ln1_b, a);
    // 2) QKV projection
    hgemm_kernel<0><<<dim3(6, kM / 128), 256>>>(a, w_in, in_b, nullptr, big, kM, 768, kC);
    // 3) windowed attention (tensor-core, ldmatrix.trans)
    attn_mma_kernel<<<kNWin, 256, kAttnSmem>>>(big, bb);
    // 4) out-proj + window-reverse + residual -> fp32 x2
    hgemm_kernel<2><<<dim3(2, kM / 128), 256>>>(bb, w_out, out_b, x, cc, kM, kC, kC);
    // 5) LN2, half out
    ln_kernel<false><<<kM / 8, 256>>>(cc, ln2_g, ln2_b, a);
    // 6) MLP up + exact GELU
    hgemm_kernel<1><<<dim3(8, kM / 128), 256>>>(a, w_1, b1, nullptr, big, kM, kHid, kC);
    // 7) MLP down + residual -> fp32 final output
    hgemm_kernel<3><<<dim3(2, kM / 128), 256>>>(big, w_2, b2, cc, out, kM, kC, kHid);
}

// round 8
// speedup vs baseline: 5.3893x; 1.0497x over previous
#include <cuda_runtime.h>
#include <cuda_fp16.h>
#include <cstdint>
#include <math.h>

// ---------------- problem constants ----------------
constexpr int kB    = 8;
constexpr int kGrid = 128;
constexpr int kNtok = kGrid * kGrid;
constexpr int kC    = 256;
constexpr int kM    = kB * kNtok;     // 131072 tokens
constexpr int kHid  = 1024;
constexpr int kNWin = kB * 256;       // 2048 windows

// ---------------- scratch ----------------
__device__ __half g_big[(size_t)kM * kHid];
__device__ __half g_a  [(size_t)kM * kC];
__device__ __half g_b  [(size_t)kM * kC];
__device__ float  g_c  [(size_t)kM * kC];
__device__ __half g_w  [786432];

__device__ __forceinline__ int win_to_nat(int m) {
    int win = m >> 6;
    int t   = m & 63;
    int b   = win >> 8;
    int wi  = win & 255;
    int row = ((wi >> 4) << 3) + (t >> 3);
    int col = ((wi & 15) << 3) + (t & 7);
    return b * kNtok + row * kGrid + col;
}

__device__ __forceinline__ float gelu_exact(float x) {
    return 0.5f * x * (1.0f + erff(x * 0.70710678118654752f));
}

__device__ __forceinline__ void cpa16(__half* s, const __half* g) {
    uint32_t sa = (uint32_t)__cvta_generic_to_shared(s);
    asm volatile("cp.async.cg.shared.global [%0], [%1], 16;" :: "r"(sa), "l"(g));
}

__device__ __forceinline__ void mma16816(float* c, uint32_t a0, uint32_t a1,
                                         uint32_t a2, uint32_t a3,
                                         uint32_t b0, uint32_t b1) {
    asm volatile(
        "mma.sync.aligned.m16n8k16.row.col.f32.f16.f16.f32 "
        "{%0,%1,%2,%3}, {%4,%5,%6,%7}, {%8,%9}, {%0,%1,%2,%3};"
        : "+f"(c[0]), "+f"(c[1]), "+f"(c[2]), "+f"(c[3])
        : "r"(a0), "r"(a1), "r"(a2), "r"(a3), "r"(b0), "r"(b1));
}

__device__ __forceinline__ void ldsm4(uint32_t* r, uint32_t addr) {
    asm volatile("ldmatrix.sync.aligned.m8n8.x4.shared.b16 {%0,%1,%2,%3}, [%4];"
        : "=r"(r[0]), "=r"(r[1]), "=r"(r[2]), "=r"(r[3]) : "r"(addr));
}
__device__ __forceinline__ void ldsm4t(uint32_t* r, uint32_t addr) {
    asm volatile("ldmatrix.sync.aligned.m8n8.x4.trans.shared.b16 {%0,%1,%2,%3}, [%4];"
        : "=r"(r[0]), "=r"(r[1]), "=r"(r[2]), "=r"(r[3]) : "r"(addr));
}

__device__ __forceinline__ uint32_t packh2(float x, float y) {
    __half2 h = __floats2half2_rn(x, y);
    return *(uint32_t*)&h;
}

// ---------------- fp16 weight conversion (single launch) ----------------
__global__ __launch_bounds__(256) void cvtw_all(
    const float* __restrict__ in_w, const float* __restrict__ out_w,
    const float* __restrict__ w1, const float* __restrict__ w2,
    __half* __restrict__ o)
{
    int i = blockIdx.x * 256 + threadIdx.x;
    const float* src;
    int off;
    if (i < 196608)      { src = in_w;  off = i; }
    else if (i < 262144) { src = out_w; off = i - 196608; }
    else if (i < 524288) { src = w1;    off = i - 262144; }
    else                 { src = w2;    off = i - 524288; }
    o[i] = __float2half(src[off]);
}

// ---------------- LayerNorm: one warp per row, fp32 in, fp16 out ----------
template <bool REMAP_IN>
__global__ __launch_bounds__(256) void ln_kernel(
    const float* __restrict__ in, const float* __restrict__ g,
    const float* __restrict__ b, __half* __restrict__ out)
{
    int row  = blockIdx.x * 8 + (threadIdx.x >> 5);
    int lane = threadIdx.x & 31;
    int src  = REMAP_IN ? win_to_nat(row) : row;

    const float4* p = (const float4*)(in + (size_t)src * kC);
    float4 v0 = p[lane];
    float4 v1 = p[lane + 32];

    float s  = v0.x + v0.y + v0.z + v0.w + v1.x + v1.y + v1.z + v1.w;
    float s2 = v0.x*v0.x + v0.y*v0.y + v0.z*v0.z + v0.w*v0.w
             + v1.x*v1.x + v1.y*v1.y + v1.z*v1.z + v1.w*v1.w;
    #pragma unroll
    for (int off = 16; off > 0; off >>= 1) {
        s  += __shfl_xor_sync(0xffffffffu, s,  off);
        s2 += __shfl_xor_sync(0xffffffffu, s2, off);
    }
    float mean = s * (1.0f / kC);
    float var  = s2 * (1.0f / kC) - mean * mean;
    float inv  = rsqrtf(var + 1e-5f);

    const float4* gp = (const float4*)g;
    const float4* bp = (const float4*)b;
    float4 g0 = gp[lane], g1 = gp[lane + 32];
    float4 b0 = bp[lane], b1 = bp[lane + 32];

    __half2 h0 = __floats2half2_rn((v0.x - mean) * inv * g0.x + b0.x,
                                   (v0.y - mean) * inv * g0.y + b0.y);
    __half2 h1 = __floats2half2_rn((v0.z - mean) * inv * g0.z + b0.z,
                                   (v0.w - mean) * inv * g0.w + b0.w);
    __half2 h2 = __floats2half2_rn((v1.x - mean) * inv * g1.x + b1.x,
                                   (v1.y - mean) * inv * g1.y + b1.y);
    __half2 h3 = __floats2half2_rn((v1.z - mean) * inv * g1.z + b1.z,
                                   (v1.w - mean) * inv * g1.w + b1.w);

    __half2* q = (__half2*)(out + (size_t)row * kC);
    q[lane * 2]          = h0;
    q[lane * 2 + 1]      = h1;
    q[64 + lane * 2]     = h2;
    q[64 + lane * 2 + 1] = h3;
}

// ---------------- fp16 GEMM v2: 3-stage cp.async + ldmatrix ----------------
// out[M,N] = A[M,K] @ W[N,K]^T + epi. 128x128 tile, 8 warps (2x4), BK=32.
// SMEM stride 40 halves (80B): ldmatrix phases conflict-free.
constexpr int kAStr   = 40;                 // halves per smem row
constexpr int kStageH = 128 * kAStr;        // 5120 halves per stage per matrix
constexpr int kGemmSmem = 3 * kStageH * 2 * 2;  // 61440 bytes

template <int EPI>
__global__ __launch_bounds__(256, 2) void hgemm_kernel(
    const __half* __restrict__ A, const __half* __restrict__ W,
    const float* __restrict__ bias, const float* __restrict__ res,
    void* __restrict__ out_v, int M, int N, int K)
{
    extern __shared__ __half sm[];
    __half* As = sm;                  // 3 stages
    __half* Bs = sm + 3 * kStageH;    // 3 stages

    const int bm   = blockIdx.y * 128;
    const int bn   = blockIdx.x * 128;
    const int tid  = threadIdx.x;
    const int warp = tid >> 5;
    const int lane = tid & 31;
    const int grp  = lane >> 2;
    const int tig  = lane & 3;
    const int wm   = warp & 1;
    const int wn   = warp >> 1;

    const __half* Ag = A + (size_t)bm * K;
    const __half* Wg = W + (size_t)bn * K;

    float c[4][4][4];
    #pragma unroll
    for (int i = 0; i < 4; i++)
        #pragma unroll
        for (int j = 0; j < 4; j++)
            #pragma unroll
            for (int r = 0; r < 4; r++) c[i][j][r] = 0.0f;

    const int T = K >> 5;  // BK = 32

    const int srow = tid >> 2;        // staging row
    const int sch  = tid & 3;         // 16B chunk within the 32-half row

    // prologue: stages 0, 1
    #pragma unroll
    for (int st = 0; st < 2; st++) {
        int k0 = st << 5;
        #pragma unroll
        for (int u = 0; u < 2; u++) {
            int row = srow + u * 64;
            cpa16(&As[st * kStageH + row * kAStr + sch * 8], Ag + (size_t)row * K + k0 + sch * 8);
            cpa16(&Bs[st * kStageH + row * kAStr + sch * 8], Wg + (size_t)row * K + k0 + sch * 8);
        }
        asm volatile("cp.async.commit_group;");
    }

    // ldmatrix lane addressing (halves, relative to stage base)
    const uint32_t smbA = (uint32_t)__cvta_generic_to_shared(As);
    const uint32_t smbB = (uint32_t)__cvta_generic_to_shared(Bs);
    const int aoff = (wm * 64 + (lane & 7) + ((lane >> 3) & 1) * 8) * kAStr
                   + ((lane >> 4) & 1) * 8;
    const int boff0 = (wn * 32 + ((lane >> 4) & 1) * 8 + (lane & 7)) * kAStr
                    + ((lane >> 3) & 1) * 8;            // jp = 0
    const int boff1 = boff0 + 16 * kAStr;               // jp = 1

    for (int t = 0; t < T; t++) {
        if (t < T - 1) asm volatile("cp.async.wait_group 1;" ::: "memory");
        else           asm volatile("cp.async.wait_group 0;" ::: "memory");
        __syncthreads();

        const int stage = t % 3;
        const uint32_t abase = smbA + (uint32_t)(stage * kStageH) * 2;
        const uint32_t bbase = smbB + (uint32_t)(stage * kStageH) * 2;

        #pragma unroll
        for (int kb = 0; kb < 2; kb++) {
            uint32_t af[4][4];
            uint32_t bq0[4], bq1[4];
            #pragma unroll
            for (int i = 0; i < 4; i++)
                ldsm4(af[i], abase + (uint32_t)(aoff + i * 16 * kAStr + kb * 16) * 2);
            ldsm4(bq0, bbase + (uint32_t)(boff0 + kb * 16) * 2);
            ldsm4(bq1, bbase + (uint32_t)(boff1 + kb * 16) * 2);

            #pragma unroll
            for (int i = 0; i < 4; i++) {
                mma16816(c[i][0], af[i][0], af[i][1], af[i][2], af[i][3], bq0[0], bq0[1]);
                mma16816(c[i][1], af[i][0], af[i][1], af[i][2], af[i][3], bq0[2], bq0[3]);
                mma16816(c[i][2], af[i][0], af[i][1], af[i][2], af[i][3], bq1[0], bq1[1]);
                mma16816(c[i][3], af[i][0], af[i][1], af[i][2], af[i][3], bq1[2], bq1[3]);
            }
        }

        // prefetch stage t+2 (writes go to buffer all warps finished reading)
        if (t + 2 < T) {
            int k0 = (t + 2) << 5;
            int st = (t + 2) % 3;
            #pragma unroll
            for (int u = 0; u < 2; u++) {
                int row = srow + u * 64;
                cpa16(&As[st * kStageH + row * kAStr + sch * 8], Ag + (size_t)row * K + k0 + sch * 8);
                cpa16(&Bs[st * kStageH + row * kAStr + sch * 8], Wg + (size_t)row * K + k0 + sch * 8);
            }
            asm volatile("cp.async.commit_group;");
        }
    }

    // ---- epilogue ----
    #pragma unroll
    for (int i = 0; i < 4; i++) {
        int mrow0 = bm + wm * 64 + i * 16 + grp;
        int mrow1 = mrow0 + 8;
        int or0 = (EPI == 2) ? win_to_nat(mrow0) : mrow0;
        int or1 = (EPI == 2) ? win_to_nat(mrow1) : mrow1;
        #pragma unroll
        for (int j = 0; j < 4; j++) {
            int col = bn + wn * 32 + j * 8 + 2 * tig;
            float2 bv = *(const float2*)&bias[col];
            float v0 = c[i][j][0] + bv.x;
            float v1 = c[i][j][1] + bv.y;
            float v2 = c[i][j][2] + bv.x;
            float v3 = c[i][j][3] + bv.y;
            if (EPI == 0) {
                __half* out = (__half*)out_v;
                *(__half2*)&out[(size_t)or0 * N + col] = __floats2half2_rn(v0, v1);
                *(__half2*)&out[(size_t)or1 * N + col] = __floats2half2_rn(v2, v3);
            } else if (EPI == 1) {
                __half* out = (__half*)out_v;
                *(__half2*)&out[(size_t)or0 * N + col] =
                    __floats2half2_rn(gelu_exact(v0), gelu_exact(v1));
                *(__half2*)&out[(size_t)or1 * N + col] =
                    __floats2half2_rn(gelu_exact(v2), gelu_exact(v3));
            } else {
                float* out = (float*)out_v;
                float2 r0 = *(const float2*)&res[(size_t)or0 * 256 + col];
                float2 r1 = *(const float2*)&res[(size_t)or1 * 256 + col];
                *(float2*)&out[(size_t)or0 * N + col] = make_float2(v0 + r0.x, v1 + r0.y);
                *(float2*)&out[(size_t)or1 * N + col] = make_float2(v2 + r1.x, v3 + r1.y);
            }
        }
    }
}

// ---------------- mma window attention (unchanged from round 6) -----------
constexpr int kQKstr = 272;
constexpr int kVstr  = 264;
constexpr int kQoff  = 0;
constexpr int kKoff  = 64 * kQKstr;
constexpr int kVoff  = 2 * 64 * kQKstr;
constexpr int kAttnSmem = (kVoff + 64 * kVstr) * 2;

__global__ __launch_bounds__(256, 2) void attn_mma_kernel(
    const __half* __restrict__ qkv, __half* __restrict__ o)
{
    extern __shared__ __half sm[];
    const int tid  = threadIdx.x;
    const int win  = blockIdx.x;
    const int h    = tid >> 5;
    const int lane = tid & 31;
    const int grp  = lane >> 2;
    const int tig  = lane & 3;

    const __half* gbase = qkv + (size_t)win * 64 * 768;
    #pragma unroll
    for (int u = 0; u < 8; u++) {
        int idx = tid + u * 256;
        int t   = idx >> 5;
        int c8  = (idx & 31) << 3;
        const __half* gp = gbase + t * 768 + c8;
        *(uint4*)&sm[kQoff + t * kQKstr + c8] = *(const uint4*)gp;
        *(uint4*)&sm[kKoff + t * kQKstr + c8] = *(const uint4*)(gp + 256);
        *(uint4*)&sm[kVoff + t * kVstr  + c8] = *(const uint4*)(gp + 512);
    }
    __syncthreads();

    uint32_t bf[4][4][2];
    {
        const uint32_t smb = (uint32_t)__cvta_generic_to_shared(sm);
        int srow = (lane & 7) + ((lane >> 3) & 1) * 8;
        int dcol = h * 32 + (lane >> 4) * 8;
        #pragma unroll
        for (int kk = 0; kk < 4; kk++) {
            #pragma unroll
            for (int jp = 0; jp < 2; jp++) {
                uint32_t addr = smb +
                    (uint32_t)(kVoff + (kk * 16 + srow) * kVstr + dcol + jp * 16) * 2;
                uint32_t r[4];
                ldsm4t(r, addr);
                bf[kk][jp * 2 + 0][0] = r[0];
                bf[kk][jp * 2 + 0][1] = r[1];
                bf[kk][jp * 2 + 1][0] = r[2];
                bf[kk][jp * 2 + 1][1] = r[3];
            }
        }
    }

    const float scale = 0.17677669529663687f;

    #pragma unroll
    for (int i = 0; i < 4; i++) {
        float s[8][4];
        #pragma unroll
        for (int j = 0; j < 8; j++)
            #pragma unroll
            for (int r = 0; r < 4; r++) s[j][r] = 0.0f;

        #pragma unroll
        for (int kb = 0; kb < 2; kb++) {
            const int kcol = h * 32 + kb * 16 + tig * 4;
            const int r = i * 16 + grp;
            uint2 qlo = *(const uint2*)&sm[kQoff + r * kQKstr + kcol];
            uint2 qhi = *(const uint2*)&sm[kQoff + (r + 8) * kQKstr + kcol];
            #pragma unroll
            for (int j = 0; j < 8; j++) {
                uint2 kv = *(const uint2*)&sm[kKoff + (j * 8 + grp) * kQKstr + kcol];
                mma16816(s[j], qlo.x, qhi.x, qlo.y, qhi.y, kv.x, kv.y);
            }
        }

        float mx0 = -1e30f, mx1 = -1e30f;
        #pragma unroll
        for (int j = 0; j < 8; j++) {
            mx0 = fmaxf(mx0, fmaxf(s[j][0], s[j][1]));
            mx1 = fmaxf(mx1, fmaxf(s[j][2], s[j][3]));
        }
        mx0 = fmaxf(mx0, __shfl_xor_sync(0xffffffffu, mx0, 1));
        mx0 = fmaxf(mx0, __shfl_xor_sync(0xffffffffu, mx0, 2));
        mx1 = fmaxf(mx1, __shfl_xor_sync(0xffffffffu, mx1, 1));
        mx1 = fmaxf(mx1, __shfl_xor_sync(0xffffffffu, mx1, 2));

        float sum0 = 0.0f, sum1 = 0.0f;
        #pragma unroll
        for (int j = 0; j < 8; j++) {
            s[j][0] = __expf((s[j][0] - mx0) * scale);
            s[j][1] = __expf((s[j][1] - mx0) * scale);
            s[j][2] = __expf((s[j][2] - mx1) * scale);
            s[j][3] = __expf((s[j][3] - mx1) * scale);
            sum0 += s[j][0] + s[j][1];
            sum1 += s[j][2] + s[j][3];
        }
        sum0 += __shfl_xor_sync(0xffffffffu, sum0, 1);
        sum0 += __shfl_xor_sync(0xffffffffu, sum0, 2);
        sum1 += __shfl_xor_sync(0xffffffffu, sum1, 1);
        sum1 += __shfl_xor_sync(0xffffffffu, sum1, 2);
        float inv0 = 1.0f / sum0;
        float inv1 = 1.0f / sum1;

        uint32_t ph0[8], ph1[8];
        #pragma unroll
        for (int j = 0; j < 8; j++) {
            ph0[j] = packh2(s[j][0] * inv0, s[j][1] * inv0);
            ph1[j] = packh2(s[j][2] * inv1, s[j][3] * inv1);
        }

        float oa[4][4];
        #pragma unroll
        for (int jn = 0; jn < 4; jn++)
            #pragma unroll
            for (int r = 0; r < 4; r++) oa[jn][r] = 0.0f;

        #pragma unroll
        for (int kk = 0; kk < 4; kk++)
            #pragma unroll
            for (int jn = 0; jn < 4; jn++)
                mma16816(oa[jn], ph0[2 * kk], ph1[2 * kk],
                         ph0[2 * kk + 1], ph1[2 * kk + 1],
                         bf[kk][jn][0], bf[kk][jn][1]);

        int gr = win * 64 + i * 16 + grp;
        #pragma unroll
        for (int jn = 0; jn < 4; jn++) {
            int col = h * 32 + jn * 8 + tig * 2;
            *(__half2*)&o[(size_t)gr * 256 + col] =
                __floats2half2_rn(oa[jn][0], oa[jn][1]);
            *(__half2*)&o[(size_t)(gr + 8) * 256 + col] =
                __floats2half2_rn(oa[jn][2], oa[jn][3]);
        }
    }
}

// ---------------- launch ----------------
extern "C" void kernel_launch(void* const* d_in, const int* in_sizes, int n_in,
                              void* d_out, int out_size)
{
    const float* x     = (const float*)d_in[0];
    const float* ln1_g = (const float*)d_in[1];
    const float* ln1_b = (const float*)d_in[2];
    const float* in_w  = (const float*)d_in[3];
    const float* in_b  = (const float*)d_in[4];
    const float* out_w = (const float*)d_in[5];
    const float* out_b = (const float*)d_in[6];
    const float* ln2_g = (const float*)d_in[7];
    const float* ln2_b = (const float*)d_in[8];
    const float* w1    = (const float*)d_in[9];
    const float* b1    = (const float*)d_in[10];
    const float* w2    = (const float*)d_in[11];
    const float* b2    = (const float*)d_in[12];
    float* out = (float*)d_out;

    __half *big, *a, *bb, *w;
    float *cc;
    cudaGetSymbolAddress((void**)&big, g_big);
    cudaGetSymbolAddress((void**)&a,   g_a);
    cudaGetSymbolAddress((void**)&bb,  g_b);
    cudaGetSymbolAddress((void**)&cc,  g_c);
    cudaGetSymbolAddress((void**)&w,   g_w);

    __half* w_in  = w;
    __half* w_out = w + 196608;
    __half* w_1   = w + 262144;
    __half* w_2   = w + 524288;

    cudaFuncSetAttribute(attn_mma_kernel,
                         cudaFuncAttributeMaxDynamicSharedMemorySize, kAttnSmem);
    cudaFuncSetAttribute(hgemm_kernel<0>,
                         cudaFuncAttributeMaxDynamicSharedMemorySize, kGemmSmem);
    cudaFuncSetAttribute(hgemm_kernel<1>,
                         cudaFuncAttributeMaxDynamicSharedMemorySize, kGemmSmem);
    cudaFuncSetAttribute(hgemm_kernel<2>,
                         cudaFuncAttributeMaxDynamicSharedMemorySize, kGemmSmem);
    cudaFuncSetAttribute(hgemm_kernel<3>,
                         cudaFuncAttributeMaxDynamicSharedMemorySize, kGemmSmem);

    // 0) fp16 weights (single launch)
    cvtw_all<<<3072, 256>>>(in_w, out_w, w1, w2, w);
    // 1) LN1, natural -> windowed order, half out
    ln_kernel<true><<<kM / 8, 256>>>(x, ln1_g, ln1_b, a);
    // 2) QKV projection
    hgemm_kernel<0><<<dim3(6, kM / 128), 256, kGemmSmem>>>(a, w_in, in_b, nullptr, big, kM, 768, kC);
    // 3) windowed attention (tensor-core)
    attn_mma_kernel<<<kNWin, 256, kAttnSmem>>>(big, bb);
    // 4) out-proj + window-reverse + residual -> fp32 x2
    hgemm_kernel<2><<<dim3(2, kM / 128), 256, kGemmSmem>>>(bb, w_out, out_b, x, cc, kM, kC, kC);
    // 5) LN2, half out
    ln_kernel<false><<<kM / 8, 256>>>(cc, ln2_g, ln2_b, a);
    // 6) MLP up + exact GELU
    hgemm_kernel<1><<<dim3(8, kM / 128), 256, kGemmSmem>>>(a, w_1, b1, nullptr, big, kM, kHid, kC);
    // 7) MLP down + residual -> fp32 final output
    hgemm_kernel<3><<<dim3(2, kM / 128), 256, kGemmSmem>>>(big, w_2, b2, cc, out, kM, kC, kHid);
}

// round 10
// speedup vs baseline: 5.4013x; 1.0022x over previous
#include <cuda_runtime.h>
#include <cuda_fp16.h>
#include <cstdint>
#include <math.h>

// ---------------- problem constants ----------------
constexpr int kB    = 8;
constexpr int kGrid = 128;
constexpr int kNtok = kGrid * kGrid;
constexpr int kC    = 256;
constexpr int kM    = kB * kNtok;     // 131072 tokens
constexpr int kHid  = 1024;
constexpr int kNWin = kB * 256;       // 2048 windows

// ---------------- scratch ----------------
__device__ __half g_big[(size_t)kM * kHid];
__device__ __half g_a  [(size_t)kM * kC];
__device__ __half g_b  [(size_t)kM * kC];
__device__ float  g_c  [(size_t)kM * kC];
__device__ __half g_w  [786432];

__device__ __forceinline__ int win_to_nat(int m) {
    int win = m >> 6;
    int t   = m & 63;
    int b   = win >> 8;
    int wi  = win & 255;
    int row = ((wi >> 4) << 3) + (t >> 3);
    int col = ((wi & 15) << 3) + (t & 7);
    return b * kNtok + row * kGrid + col;
}

__device__ __forceinline__ float gelu_exact(float x) {
    return 0.5f * x * (1.0f + erff(x * 0.70710678118654752f));
}

__device__ __forceinline__ void cpa16(__half* s, const __half* g) {
    uint32_t sa = (uint32_t)__cvta_generic_to_shared(s);
    asm volatile("cp.async.cg.shared.global [%0], [%1], 16;" :: "r"(sa), "l"(g));
}

__device__ __forceinline__ void mma16816(float* c, uint32_t a0, uint32_t a1,
                                         uint32_t a2, uint32_t a3,
                                         uint32_t b0, uint32_t b1) {
    asm volatile(
        "mma.sync.aligned.m16n8k16.row.col.f32.f16.f16.f32 "
        "{%0,%1,%2,%3}, {%4,%5,%6,%7}, {%8,%9}, {%0,%1,%2,%3};"
        : "+f"(c[0]), "+f"(c[1]), "+f"(c[2]), "+f"(c[3])
        : "r"(a0), "r"(a1), "r"(a2), "r"(a3), "r"(b0), "r"(b1));
}

__device__ __forceinline__ void ldsm4(uint32_t* r, uint32_t addr) {
    asm volatile("ldmatrix.sync.aligned.m8n8.x4.shared.b16 {%0,%1,%2,%3}, [%4];"
        : "=r"(r[0]), "=r"(r[1]), "=r"(r[2]), "=r"(r[3]) : "r"(addr));
}
__device__ __forceinline__ void ldsm4t(uint32_t* r, uint32_t addr) {
    asm volatile("ldmatrix.sync.aligned.m8n8.x4.trans.shared.b16 {%0,%1,%2,%3}, [%4];"
        : "=r"(r[0]), "=r"(r[1]), "=r"(r[2]), "=r"(r[3]) : "r"(addr));
}

__device__ __forceinline__ uint32_t packh2(float x, float y) {
    __half2 h = __floats2half2_rn(x, y);
    return *(uint32_t*)&h;
}

// ---------------- fp16 weight conversion (single launch) ----------------
__global__ __launch_bounds__(256) void cvtw_all(
    const float* __restrict__ in_w, const float* __restrict__ out_w,
    const float* __restrict__ w1, const float* __restrict__ w2,
    __half* __restrict__ o)
{
    int i = blockIdx.x * 256 + threadIdx.x;
    const float* src;
    int off;
    if (i < 196608)      { src = in_w;  off = i; }
    else if (i < 262144) { src = out_w; off = i - 196608; }
    else if (i < 524288) { src = w1;    off = i - 262144; }
    else                 { src = w2;    off = i - 524288; }
    o[i] = __float2half(src[off]);
}

// ---------------- LayerNorm (LN1 only): natural -> windowed, half out -----
__global__ __launch_bounds__(256) void ln_kernel(
    const float* __restrict__ in, const float* __restrict__ g,
    const float* __restrict__ b, __half* __restrict__ out)
{
    int row  = blockIdx.x * 8 + (threadIdx.x >> 5);
    int lane = threadIdx.x & 31;
    int src  = win_to_nat(row);

    const float4* p = (const float4*)(in + (size_t)src * kC);
    float4 v0 = p[lane];
    float4 v1 = p[lane + 32];

    float s  = v0.x + v0.y + v0.z + v0.w + v1.x + v1.y + v1.z + v1.w;
    float s2 = v0.x*v0.x + v0.y*v0.y + v0.z*v0.z + v0.w*v0.w
             + v1.x*v1.x + v1.y*v1.y + v1.z*v1.z + v1.w*v1.w;
    #pragma unroll
    for (int off = 16; off > 0; off >>= 1) {
        s  += __shfl_xor_sync(0xffffffffu, s,  off);
        s2 += __shfl_xor_sync(0xffffffffu, s2, off);
    }
    float mean = s * (1.0f / kC);
    float var  = s2 * (1.0f / kC) - mean * mean;
    float inv  = rsqrtf(var + 1e-5f);

    const float4* gp = (const float4*)g;
    const float4* bp = (const float4*)b;
    float4 g0 = gp[lane], g1 = gp[lane + 32];
    float4 b0 = bp[lane], b1 = bp[lane + 32];

    __half2 h0 = __floats2half2_rn((v0.x - mean) * inv * g0.x + b0.x,
                                   (v0.y - mean) * inv * g0.y + b0.y);
    __half2 h1 = __floats2half2_rn((v0.z - mean) * inv * g0.z + b0.z,
                                   (v0.w - mean) * inv * g0.w + b0.w);
    __half2 h2 = __floats2half2_rn((v1.x - mean) * inv * g1.x + b1.x,
                                   (v1.y - mean) * inv * g1.y + b1.y);
    __half2 h3 = __floats2half2_rn((v1.z - mean) * inv * g1.z + b1.z,
                                   (v1.w - mean) * inv * g1.w + b1.w);

    __half2* q = (__half2*)(out + (size_t)row * kC);
    q[lane * 2]          = h0;
    q[lane * 2 + 1]      = h1;
    q[64 + lane * 2]     = h2;
    q[64 + lane * 2 + 1] = h3;
}

// ---------------- fp16 GEMM: 3-stage cp.async + ldmatrix (EPI 0,1,3) ------
constexpr int kAStr   = 40;
constexpr int kStageH = 128 * kAStr;
constexpr int kGemmSmem = 3 * kStageH * 2 * 2;  // 61440 bytes

template <int EPI>
__global__ __launch_bounds__(256, 2) void hgemm_kernel(
    const __half* __restrict__ A, const __half* __restrict__ W,
    const float* __restrict__ bias, const float* __restrict__ res,
    void* __restrict__ out_v, int M, int N, int K)
{
    extern __shared__ __half sm[];
    __half* As = sm;
    __half* Bs = sm + 3 * kStageH;

    const int bm   = blockIdx.y * 128;
    const int bn   = blockIdx.x * 128;
    const int tid  = threadIdx.x;
    const int warp = tid >> 5;
    const int lane = tid & 31;
    const int grp  = lane >> 2;
    const int tig  = lane & 3;
    const int wm   = warp & 1;
    const int wn   = warp >> 1;

    const __half* Ag = A + (size_t)bm * K;
    const __half* Wg = W + (size_t)bn * K;

    float c[4][4][4];
    #pragma unroll
    for (int i = 0; i < 4; i++)
        #pragma unroll
        for (int j = 0; j < 4; j++)
            #pragma unroll
            for (int r = 0; r < 4; r++) c[i][j][r] = 0.0f;

    const int T = K >> 5;

    const int srow = tid >> 2;
    const int sch  = tid & 3;

    #pragma unroll
    for (int st = 0; st < 2; st++) {
        int k0 = st << 5;
        #pragma unroll
        for (int u = 0; u < 2; u++) {
            int row = srow + u * 64;
            cpa16(&As[st * kStageH + row * kAStr + sch * 8], Ag + (size_t)row * K + k0 + sch * 8);
            cpa16(&Bs[st * kStageH + row * kAStr + sch * 8], Wg + (size_t)row * K + k0 + sch * 8);
        }
        asm volatile("cp.async.commit_group;");
    }

    const uint32_t smbA = (uint32_t)__cvta_generic_to_shared(As);
    const uint32_t smbB = (uint32_t)__cvta_generic_to_shared(Bs);
    const int aoff = (wm * 64 + (lane & 7) + ((lane >> 3) & 1) * 8) * kAStr
                   + ((lane >> 4) & 1) * 8;
    const int boff0 = (wn * 32 + ((lane >> 4) & 1) * 8 + (lane & 7)) * kAStr
                    + ((lane >> 3) & 1) * 8;
    const int boff1 = boff0 + 16 * kAStr;

    for (int t = 0; t < T; t++) {
        if (t < T - 1) asm volatile("cp.async.wait_group 1;" ::: "memory");
        else           asm volatile("cp.async.wait_group 0;" ::: "memory");
        __syncthreads();

        const int stage = t % 3;
        const uint32_t abase = smbA + (uint32_t)(stage * kStageH) * 2;
        const uint32_t bbase = smbB + (uint32_t)(stage * kStageH) * 2;

        #pragma unroll
        for (int kb = 0; kb < 2; kb++) {
            uint32_t af[4][4];
            uint32_t bq0[4], bq1[4];
            #pragma unroll
            for (int i = 0; i < 4; i++)
                ldsm4(af[i], abase + (uint32_t)(aoff + i * 16 * kAStr + kb * 16) * 2);
            ldsm4(bq0, bbase + (uint32_t)(boff0 + kb * 16) * 2);
            ldsm4(bq1, bbase + (uint32_t)(boff1 + kb * 16) * 2);

            #pragma unroll
            for (int i = 0; i < 4; i++) {
                mma16816(c[i][0], af[i][0], af[i][1], af[i][2], af[i][3], bq0[0], bq0[1]);
                mma16816(c[i][1], af[i][0], af[i][1], af[i][2], af[i][3], bq0[2], bq0[3]);
                mma16816(c[i][2], af[i][0], af[i][1], af[i][2], af[i][3], bq1[0], bq1[1]);
                mma16816(c[i][3], af[i][0], af[i][1], af[i][2], af[i][3], bq1[2], bq1[3]);
            }
        }

        if (t + 2 < T) {
            int k0 = (t + 2) << 5;
            int st = (t + 2) % 3;
            #pragma unroll
            for (int u = 0; u < 2; u++) {
                int row = srow + u * 64;
                cpa16(&As[st * kStageH + row * kAStr + sch * 8], Ag + (size_t)row * K + k0 + sch * 8);
                cpa16(&Bs[st * kStageH + row * kAStr + sch * 8], Wg + (size_t)row * K + k0 + sch * 8);
            }
            asm volatile("cp.async.commit_group;");
        }
    }

    #pragma unroll
    for (int i = 0; i < 4; i++) {
        int mrow0 = bm + wm * 64 + i * 16 + grp;
        int mrow1 = mrow0 + 8;
        #pragma unroll
        for (int j = 0; j < 4; j++) {
            int col = bn + wn * 32 + j * 8 + 2 * tig;
            float2 bv = *(const float2*)&bias[col];
            float v0 = c[i][j][0] + bv.x;
            float v1 = c[i][j][1] + bv.y;
            float v2 = c[i][j][2] + bv.x;
            float v3 = c[i][j][3] + bv.y;
            if (EPI == 0) {
                __half* out = (__half*)out_v;
                *(__half2*)&out[(size_t)mrow0 * N + col] = __floats2half2_rn(v0, v1);
                *(__half2*)&out[(size_t)mrow1 * N + col] = __floats2half2_rn(v2, v3);
            } else if (EPI == 1) {
                __half* out = (__half*)out_v;
                *(__half2*)&out[(size_t)mrow0 * N + col] =
                    __floats2half2_rn(gelu_exact(v0), gelu_exact(v1));
                *(__half2*)&out[(size_t)mrow1 * N + col] =
                    __floats2half2_rn(gelu_exact(v2), gelu_exact(v3));
            } else {
                float* out = (float*)out_v;
                float2 r0 = *(const float2*)&res[(size_t)mrow0 * 256 + col];
                float2 r1 = *(const float2*)&res[(size_t)mrow1 * 256 + col];
                *(float2*)&out[(size_t)mrow0 * N + col] = make_float2(v0 + r0.x, v1 + r0.y);
                *(float2*)&out[(size_t)mrow1 * N + col] = make_float2(v2 + r1.x, v3 + r1.y);
            }
        }
    }
}

// ---- fused out-proj + window-reverse + residual + LN2 ---------------------
// Tile 64 (m) x 256 (n), grid = kM/64. Writes x2 (fp32, natural order) AND
// LN2 output (half, natural order). 8 warps, each 64x32 cols.
constexpr int kFStageA = 64 * kAStr;    // 2560 halves
constexpr int kFStageB = 256 * kAStr;   // 10240 halves
constexpr int kFusedSmem = 3 * (kFStageA + kFStageB) * 2;  // 76800 bytes

__global__ __launch_bounds__(256, 2) void hgemm_oproj_ln2(
    const __half* __restrict__ A, const __half* __restrict__ W,
    const float* __restrict__ bias, const float* __restrict__ x,
    const float* __restrict__ g2, const float* __restrict__ b2,
    float* __restrict__ x2out, __half* __restrict__ lnout)
{
    extern __shared__ __half sm[];
    __half* As = sm;                       // 3 x 2560
    __half* Bs = sm + 3 * kFStageA;        // 3 x 10240
    float*  red = (float*)sm;              // reused for epilogue reduction

    const int K = 256;
    const int bm   = blockIdx.x * 64;
    const int tid  = threadIdx.x;
    const int warp = tid >> 5;
    const int lane = tid & 31;
    const int grp  = lane >> 2;
    const int tig  = lane & 3;

    const __half* Ag = A + (size_t)bm * K;

    float c[4][4][4];
    #pragma unroll
    for (int i = 0; i < 4; i++)
        #pragma unroll
        for (int j = 0; j < 4; j++)
            #pragma unroll
            for (int r = 0; r < 4; r++) c[i][j][r] = 0.0f;

    const int T = K >> 5;  // 8

    // staging: A 64 rows x 4 chunks (one per thread); B 256 rows x 4 chunks
    const int arow = tid >> 2;   // 0..63
    const int ach  = tid & 3;    // 0..3

    #pragma unroll
    for (int st = 0; st < 2; st++) {
        int k0 = st << 5;
        cpa16(&As[st * kFStageA + arow * kAStr + ach * 8],
              Ag + (size_t)arow * K + k0 + ach * 8);
        #pragma unroll
        for (int u = 0; u < 4; u++) {
            int row = arow + u * 64;
            cpa16(&Bs[st * kFStageB + row * kAStr + ach * 8],
                  W + (size_t)row * K + k0 + ach * 8);
        }
        asm volatile("cp.async.commit_group;");
    }

    const uint32_t smbA = (uint32_t)__cvta_generic_to_shared(As);
    const uint32_t smbB = (uint32_t)__cvta_generic_to_shared(Bs);
    const int aoff = ((lane & 7) + ((lane >> 3) & 1) * 8) * kAStr
                   + ((lane >> 4) & 1) * 8;
    const int boff0 = (warp * 32 + ((lane >> 4) & 1) * 8 + (lane & 7)) * kAStr
                    + ((lane >> 3) & 1) * 8;
    const int boff1 = boff0 + 16 * kAStr;

    for (int t = 0; t < T; t++) {
        if (t < T - 1) asm volatile("cp.async.wait_group 1;" ::: "memory");
        else           asm volatile("cp.async.wait_group 0;" ::: "memory");
        __syncthreads();

        const int stage = t % 3;
        const uint32_t abase = smbA + (uint32_t)(stage * kFStageA) * 2;
        const uint32_t bbase = smbB + (uint32_t)(stage * kFStageB) * 2;

        #pragma unroll
        for (int kb = 0; kb < 2; kb++) {
            uint32_t af[4][4];
            uint32_t bq0[4], bq1[4];
            #pragma unroll
            for (int i = 0; i < 4; i++)
                ldsm4(af[i], abase + (uint32_t)(aoff + i * 16 * kAStr + kb * 16) * 2);
            ldsm4(bq0, bbase + (uint32_t)(boff0 + kb * 16) * 2);
            ldsm4(bq1, bbase + (uint32_t)(boff1 + kb * 16) * 2);

            #pragma unroll
            for (int i = 0; i < 4; i++) {
                mma16816(c[i][0], af[i][0], af[i][1], af[i][2], af[i][3], bq0[0], bq0[1]);
                mma16816(c[i][1], af[i][0], af[i][1], af[i][2], af[i][3], bq0[2], bq0[3]);
                mma16816(c[i][2], af[i][0], af[i][1], af[i][2], af[i][3], bq1[0], bq1[1]);
                mma16816(c[i][3], af[i][0], af[i][1], af[i][2], af[i][3], bq1[2], bq1[3]);
            }
        }

        if (t + 2 < T) {
            int k0 = (t + 2) << 5;
            int st = (t + 2) % 3;
            cpa16(&As[st * kFStageA + arow * kAStr + ach * 8],
                  Ag + (size_t)arow * K + k0 + ach * 8);
            #pragma unroll
            for (int u = 0; u < 4; u++) {
                int row = arow + u * 64;
                cpa16(&Bs[st * kFStageB + row * kAStr + ach * 8],
                      W + (size_t)row * K + k0 + ach * 8);
            }
            asm volatile("cp.async.commit_group;");
        }
    }

    // ---- epilogue pass 1: x2 = mma + bias + shortcut; write x2; stats ----
    int orow_[8];
    #pragma unroll
    for (int i = 0; i < 4; i++) {
        orow_[i * 2]     = win_to_nat(bm + i * 16 + grp);
        orow_[i * 2 + 1] = win_to_nat(bm + i * 16 + grp + 8);
    }

    float psum[8], psq[8];
    #pragma unroll
    for (int r = 0; r < 8; r++) { psum[r] = 0.0f; psq[r] = 0.0f; }

    #pragma unroll
    for (int i = 0; i < 4; i++) {
        #pragma unroll
        for (int j = 0; j < 4; j++) {
            int col = warp * 32 + j * 8 + 2 * tig;
            float2 bv = *(const float2*)&bias[col];
            float2 r0 = *(const float2*)&x[(size_t)orow_[i*2]   * 256 + col];
            float2 r1 = *(const float2*)&x[(size_t)orow_[i*2+1] * 256 + col];
            c[i][j][0] += bv.x + r0.x;
            c[i][j][1] += bv.y + r0.y;
            c[i][j][2] += bv.x + r1.x;
            c[i][j][3] += bv.y + r1.y;
            *(float2*)&x2out[(size_t)orow_[i*2]   * 256 + col] = make_float2(c[i][j][0], c[i][j][1]);
            *(float2*)&x2out[(size_t)orow_[i*2+1] * 256 + col] = make_float2(c[i][j][2], c[i][j][3]);
            psum[i*2]   += c[i][j][0] + c[i][j][1];
            psq[i*2]    += c[i][j][0]*c[i][j][0] + c[i][j][1]*c[i][j][1];
            psum[i*2+1] += c[i][j][2] + c[i][j][3];
            psq[i*2+1]  += c[i][j][2]*c[i][j][2] + c[i][j][3]*c[i][j][3];
        }
    }

    // quad reduce (lanes differing in tig)
    #pragma unroll
    for (int r = 0; r < 8; r++) {
        psum[r] += __shfl_xor_sync(0xffffffffu, psum[r], 1);
        psum[r] += __shfl_xor_sync(0xffffffffu, psum[r], 2);
        psq[r]  += __shfl_xor_sync(0xffffffffu, psq[r], 1);
        psq[r]  += __shfl_xor_sync(0xffffffffu, psq[r], 2);
    }

    __syncthreads();   // done reading smem stages
    // red layout: [row(64)][warp(8)] float2 -> 1024 floats; rowstat at +1024
    if (tig == 0) {
        #pragma unroll
        for (int i = 0; i < 4; i++) {
            int r0 = i * 16 + grp, r1 = r0 + 8;
            red[(r0 * 8 + warp) * 2]     = psum[i*2];
            red[(r0 * 8 + warp) * 2 + 1] = psq[i*2];
            red[(r1 * 8 + warp) * 2]     = psum[i*2+1];
            red[(r1 * 8 + warp) * 2 + 1] = psq[i*2+1];
        }
    }
    __syncthreads();

    if (tid < 64) {
        float s = 0.0f, sq = 0.0f;
        #pragma unroll
        for (int wdx = 0; wdx < 8; wdx++) {
            s  += red[(tid * 8 + wdx) * 2];
            sq += red[(tid * 8 + wdx) * 2 + 1];
        }
        float mean = s * (1.0f / 256.0f);
        float var  = sq * (1.0f / 256.0f) - mean * mean;
        red[1024 + tid * 2]     = mean;
        red[1024 + tid * 2 + 1] = rsqrtf(var + 1e-5f);
    }
    __syncthreads();

    // ---- pass 2: apply LN2, write half ----
    #pragma unroll
    for (int i = 0; i < 4; i++) {
        int r0 = i * 16 + grp, r1 = r0 + 8;
        float m0 = red[1024 + r0 * 2], v0i = red[1024 + r0 * 2 + 1];
        float m1 = red[1024 + r1 * 2], v1i = red[1024 + r1 * 2 + 1];
        #pragma unroll
        for (int j = 0; j < 4; j++) {
            int col = warp * 32 + j * 8 + 2 * tig;
            float2 gg = *(const float2*)&g2[col];
            float2 bb = *(const float2*)&b2[col];
            *(__half2*)&lnout[(size_t)orow_[i*2] * 256 + col] =
                __floats2half2_rn((c[i][j][0] - m0) * v0i * gg.x + bb.x,
                                  (c[i][j][1] - m0) * v0i * gg.y + bb.y);
            *(__half2*)&lnout[(size_t)orow_[i*2+1] * 256 + col] =
                __floats2half2_rn((c[i][j][2] - m1) * v1i * gg.x + bb.x,
                                  (c[i][j][3] - m1) * v1i * gg.y + bb.y);
        }
    }
}

// ---------------- mma window attention (unchanged) ----------------
constexpr int kQKstr = 272;
constexpr int kVstr  = 264;
constexpr int kQoff  = 0;
constexpr int kKoff  = 64 * kQKstr;
constexpr int kVoff  = 2 * 64 * kQKstr;
constexpr int kAttnSmem = (kVoff + 64 * kVstr) * 2;

__global__ __launch_bounds__(256, 2) void attn_mma_kernel(
    const __half* __restrict__ qkv, __half* __restrict__ o)
{
    extern __shared__ __half sm[];
    const int tid  = threadIdx.x;
    const int win  = blockIdx.x;
    const int h    = tid >> 5;
    const int lane = tid & 31;
    const int grp  = lane >> 2;
    const int tig  = lane & 3;

    const __half* gbase = qkv + (size_t)win * 64 * 768;
    #pragma unroll
    for (int u = 0; u < 8; u++) {
        int idx = tid + u * 256;
        int t   = idx >> 5;
        int c8  = (idx & 31) << 3;
        const __half* gp = gbase + t * 768 + c8;
        *(uint4*)&sm[kQoff + t * kQKstr + c8] = *(const uint4*)gp;
        *(uint4*)&sm[kKoff + t * kQKstr + c8] = *(const uint4*)(gp + 256);
        *(uint4*)&sm[kVoff + t * kVstr  + c8] = *(const uint4*)(gp + 512);
    }
    __syncthreads();

    uint32_t bf[4][4][2];
    {
        const uint32_t smb = (uint32_t)__cvta_generic_to_shared(sm);
        int srow = (lane & 7) + ((lane >> 3) & 1) * 8;
        int dcol = h * 32 + (lane >> 4) * 8;
        #pragma unroll
        for (int kk = 0; kk < 4; kk++) {
            #pragma unroll
            for (int jp = 0; jp < 2; jp++) {
                uint32_t addr = smb +
                    (uint32_t)(kVoff + (kk * 16 + srow) * kVstr + dcol + jp * 16) * 2;
                uint32_t r[4];
                ldsm4t(r, addr);
                bf[kk][jp * 2 + 0][0] = r[0];
                bf[kk][jp * 2 + 0][1] = r[1];
                bf[kk][jp * 2 + 1][0] = r[2];
                bf[kk][jp * 2 + 1][1] = r[3];
            }
        }
    }

    const float scale = 0.17677669529663687f;

    #pragma unroll
    for (int i = 0; i < 4; i++) {
        float s[8][4];
        #pragma unroll
        for (int j = 0; j < 8; j++)
            #pragma unroll
            for (int r = 0; r < 4; r++) s[j][r] = 0.0f;

        #pragma unroll
        for (int kb = 0; kb < 2; kb++) {
            const int kcol = h * 32 + kb * 16 + tig * 4;
            const int r = i * 16 + grp;
            uint2 qlo = *(const uint2*)&sm[kQoff + r * kQKstr + kcol];
            uint2 qhi = *(const uint2*)&sm[kQoff + (r + 8) * kQKstr + kcol];
            #pragma unroll
            for (int j = 0; j < 8; j++) {
                uint2 kv = *(const uint2*)&sm[kKoff + (j * 8 + grp) * kQKstr + kcol];
                mma16816(s[j], qlo.x, qhi.x, qlo.y, qhi.y, kv.x, kv.y);
            }
        }

        float mx0 = -1e30f, mx1 = -1e30f;
        #pragma unroll
        for (int j = 0; j < 8; j++) {
            mx0 = fmaxf(mx0, fmaxf(s[j][0], s[j][1]));
            mx1 = fmaxf(mx1, fmaxf(s[j][2], s[j][3]));
        }
        mx0 = fmaxf(mx0, __shfl_xor_sync(0xffffffffu, mx0, 1));
        mx0 = fmaxf(mx0, __shfl_xor_sync(0xffffffffu, mx0, 2));
        mx1 = fmaxf(mx1, __shfl_xor_sync(0xffffffffu, mx1, 1));
        mx1 = fmaxf(mx1, __shfl_xor_sync(0xffffffffu, mx1, 2));

        float sum0 = 0.0f, sum1 = 0.0f;
        #pragma unroll
        for (int j = 0; j < 8; j++) {
            s[j][0] = __expf((s[j][0] - mx0) * scale);
            s[j][1] = __expf((s[j][1] - mx0) * scale);
            s[j][2] = __expf((s[j][2] - mx1) * scale);
            s[j][3] = __expf((s[j][3] - mx1) * scale);
            sum0 += s[j][0] + s[j][1];
            sum1 += s[j][2] + s[j][3];
        }
        sum0 += __shfl_xor_sync(0xffffffffu, sum0, 1);
        sum0 += __shfl_xor_sync(0xffffffffu, sum0, 2);
        sum1 += __shfl_xor_sync(0xffffffffu, sum1, 1);
        sum1 += __shfl_xor_sync(0xffffffffu, sum1, 2);
        float inv0 = 1.0f / sum0;
        float inv1 = 1.0f / sum1;

        uint32_t ph0[8], ph1[8];
        #pragma unroll
        for (int j = 0; j < 8; j++) {
            ph0[j] = packh2(s[j][0] * inv0, s[j][1] * inv0);
            ph1[j] = packh2(s[j][2] * inv1, s[j][3] * inv1);
        }

        float oa[4][4];
        #pragma unroll
        for (int jn = 0; jn < 4; jn++)
            #pragma unroll
            for (int r = 0; r < 4; r++) oa[jn][r] = 0.0f;

        #pragma unroll
        for (int kk = 0; kk < 4; kk++)
            #pragma unroll
            for (int jn = 0; jn < 4; jn++)
                mma16816(oa[jn], ph0[2 * kk], ph1[2 * kk],
                         ph0[2 * kk + 1], ph1[2 * kk + 1],
                         bf[kk][jn][0], bf[kk][jn][1]);

        int gr = win * 64 + i * 16 + grp;
        #pragma unroll
        for (int jn = 0; jn < 4; jn++) {
            int col = h * 32 + jn * 8 + tig * 2;
            *(__half2*)&o[(size_t)gr * 256 + col] =
                __floats2half2_rn(oa[jn][0], oa[jn][1]);
            *(__half2*)&o[(size_t)(gr + 8) * 256 + col] =
                __floats2half2_rn(oa[jn][2], oa[jn][3]);
        }
    }
}

// ---------------- launch ----------------
extern "C" void kernel_launch(void* const* d_in, const int* in_sizes, int n_in,
                              void* d_out, int out_size)
{
    const float* x     = (const float*)d_in[0];
    const float* ln1_g = (const float*)d_in[1];
    const float* ln1_b = (const float*)d_in[2];
    const float* in_w  = (const float*)d_in[3];
    const float* in_b  = (const float*)d_in[4];
    const float* out_w = (const float*)d_in[5];
    const float* out_b = (const float*)d_in[6];
    const float* ln2_g = (const float*)d_in[7];
    const float* ln2_b = (const float*)d_in[8];
    const float* w1    = (const float*)d_in[9];
    const float* b1    = (const float*)d_in[10];
    const float* w2    = (const float*)d_in[11];
    const float* b2    = (const float*)d_in[12];
    float* out = (float*)d_out;

    __half *big, *a, *bb, *w;
    float *cc;
    cudaGetSymbolAddress((void**)&big, g_big);
    cudaGetSymbolAddress((void**)&a,   g_a);
    cudaGetSymbolAddress((void**)&bb,  g_b);
    cudaGetSymbolAddress((void**)&cc,  g_c);
    cudaGetSymbolAddress((void**)&w,   g_w);

    __half* w_in  = w;
    __half* w_out = w + 196608;
    __half* w_1   = w + 262144;
    __half* w_2   = w + 524288;

    cudaFuncSetAttribute(attn_mma_kernel,
                         cudaFuncAttributeMaxDynamicSharedMemorySize, kAttnSmem);
    cudaFuncSetAttribute(hgemm_kernel<0>,
                         cudaFuncAttributeMaxDynamicSharedMemorySize, kGemmSmem);
    cudaFuncSetAttribute(hgemm_kernel<1>,
                         cudaFuncAttributeMaxDynamicSharedMemorySize, kGemmSmem);
    cudaFuncSetAttribute(hgemm_kernel<3>,
                         cudaFuncAttributeMaxDynamicSharedMemorySize, kGemmSmem);
    cudaFuncSetAttribute(hgemm_oproj_ln2,
                         cudaFuncAttributeMaxDynamicSharedMemorySize, kFusedSmem);

    // 0) fp16 weights (single launch)
    cvtw_all<<<3072, 256>>>(in_w, out_w, w1, w2, w);
    // 1) LN1, natural -> windowed order, half out
    ln_kernel<<<kM / 8, 256>>>(x, ln1_g, ln1_b, a);
    // 2) QKV projection
    hgemm_kernel<0><<<dim3(6, kM / 128), 256, kGemmSmem>>>(a, w_in, in_b, nullptr, big, kM, 768, kC);
    // 3) windowed attention (tensor-core)
    attn_mma_kernel<<<kNWin, 256, kAttnSmem>>>(big, bb);
    // 4) out-proj + window-reverse + residual + LN2 (fused)
    hgemm_oproj_ln2<<<kM / 64, 256, kFusedSmem>>>(bb, w_out, out_b, x, ln2_g, ln2_b, cc, a);
    // 5) MLP up + exact GELU
    hgemm_kernel<1><<<dim3(8, kM / 128), 256, kGemmSmem>>>(a, w_1, b1, nullptr, big, kM, kHid, kC);
    // 6) MLP down + residual -> fp32 final output
    hgemm_kernel<3><<<dim3(2, kM / 128), 256, kGemmSmem>>>(big, w_2, b2, cc, out, kM, kC, kHid);
}